// round 8
// baseline (speedup 1.0000x reference)
#include <cuda_runtime.h>
#include <cuda_bf16.h>
#include <cstdint>
#include <math.h>

#define BB 8
#define NSEQ 2048
#define DDIM 512
#define MFLAT (BB*NSEQ)

// ---------------- scratch (device globals: allocation-free) ----------------
__device__ __nv_bfloat16 g_qry_hi[MFLAT*DDIM], g_qry_lo[MFLAT*DDIM];
__device__ __nv_bfloat16 g_ctx_hi[MFLAT*DDIM], g_ctx_lo[MFLAT*DDIM];
__device__ __nv_bfloat16 g_wq_hi[DDIM*DDIM],  g_wq_lo[DDIM*DDIM];
__device__ __nv_bfloat16 g_wv_hi[DDIM*DDIM],  g_wv_lo[DDIM*DDIM];
__device__ __nv_bfloat16 g_wo_hi[DDIM*DDIM],  g_wo_lo[DDIM*DDIM];
__device__ __nv_bfloat16 g_q_hi[MFLAT*DDIM],  g_q_lo[MFLAT*DDIM];
__device__ __nv_bfloat16 g_vT_hi[MFLAT*DDIM], g_vT_lo[MFLAT*DDIM];
__device__ float         g_s[(size_t)BB*NSEQ*NSEQ];
__device__ __nv_bfloat16 g_attn_hi[(size_t)BB*NSEQ*NSEQ], g_attn_lo[(size_t)BB*NSEQ*NSEQ];
__device__ __nv_bfloat16 g_h_hi[MFLAT*DDIM],  g_h_lo[MFLAT*DDIM];

// ---------------- helpers ----------------
__device__ __forceinline__ uint32_t smem_u32(const void* p){
    uint32_t a;
    asm("{ .reg .u64 t; cvta.to.shared.u64 t, %1; cvt.u32.u64 %0, t; }" : "=r"(a) : "l"(p));
    return a;
}
__device__ __forceinline__ void split2(float v, __nv_bfloat16& h, __nv_bfloat16& l){
    h = __float2bfloat16(v);
    l = __float2bfloat16(v - __bfloat162float(h));
}

#define CP_ASYNC16(sm, gm) \
    asm volatile("cp.async.cg.shared.global [%0], [%1], 16;" :: "r"(sm), "l"(gm))
#define CP_COMMIT() asm volatile("cp.async.commit_group;" ::: "memory")
#define CP_WAIT1()  asm volatile("cp.async.wait_group 1;" ::: "memory")
#define CP_WAIT0()  asm volatile("cp.async.wait_group 0;" ::: "memory")

__device__ __forceinline__ void ldmatrix_x4(uint32_t& r0, uint32_t& r1, uint32_t& r2, uint32_t& r3, uint32_t addr){
    asm volatile("ldmatrix.sync.aligned.m8n8.x4.shared.b16 {%0,%1,%2,%3}, [%4];"
        : "=r"(r0), "=r"(r1), "=r"(r2), "=r"(r3) : "r"(addr));
}
__device__ __forceinline__ void mma_bf16(float* c, const uint32_t* a, const uint32_t* b){
    asm volatile(
        "mma.sync.aligned.m16n8k16.row.col.f32.bf16.bf16.f32 "
        "{%0,%1,%2,%3}, {%4,%5,%6,%7}, {%8,%9}, {%0,%1,%2,%3};"
        : "+f"(c[0]), "+f"(c[1]), "+f"(c[2]), "+f"(c[3])
        : "r"(a[0]), "r"(a[1]), "r"(a[2]), "r"(a[3]), "r"(b[0]), "r"(b[1]));
}

// ---------------- HMMA GEMM (CTA tile 128x256, warp tile 64x64) ----------------
// C[128x256 tile] = alpha * sum over 3 segments of Aseg[M,K] @ Bseg[N,K]^T (+ bias)
// Segments: (Ahi,Bhi), (Ahi,Blo), (Alo,Bhi)  -> split-bf16 fp32 emulation.
// MODE 0: fp32 out. MODE 1: split bf16 out. MODE 2: split bf16 out, transposed
//         per-batch (v^T layout [DDIM, NSEQ]); requires N==DDIM, flat M, z==1.
// BK=32, 3-stage cp.async pipeline, ONE __syncthreads per iteration.
// Row pitch 80B: conflict-free ldmatrix.
#define PITCH 80
#define ATILEB (128*PITCH)           // 10240 B
#define BTILEB (256*PITCH)           // 20480 B
#define STAGEB (ATILEB+BTILEB)       // 30720 B
#define NSTAGE 3
#define SMEM_G (NSTAGE*STAGEB)       // 92160 B

template<int MODE>
__global__ __launch_bounds__(256, 1)
void mma_gemm(const __nv_bfloat16* __restrict__ Ahi, const __nv_bfloat16* __restrict__ Alo,
              const __nv_bfloat16* __restrict__ Bhi, const __nv_bfloat16* __restrict__ Blo,
              const float* __restrict__ bias,
              float* __restrict__ outF, __nv_bfloat16* __restrict__ outHi, __nv_bfloat16* __restrict__ outLo,
              int M, int N, int K, float alpha,
              long sA, long sB, long sC)
{
    extern __shared__ __align__(128) char smem[];

    const int tid  = threadIdx.x;
    const int warp = tid >> 5;
    const int lane = tid & 31;
    const int warpM = warp >> 2;   // 0..1  (64 rows each)
    const int warpN = warp & 3;    // 0..3  (64 cols each)

    const int z = blockIdx.z;
    Ahi += (long)z * sA;  Alo += (long)z * sA;
    Bhi += (long)z * sB;  Blo += (long)z * sB;
    if (MODE == 0) { outF += (long)z * sC; }
    else { outHi += (long)z * sC; outLo += (long)z * sC; }

    const int rowBase = blockIdx.y * 128;
    const int colBase = blockIdx.x * 256;

    const uint32_t smBase = smem_u32(smem);

    const __nv_bfloat16* Aseg[3] = {Ahi, Ahi, Alo};
    const __nv_bfloat16* Bseg[3] = {Bhi, Blo, Bhi};
    const int tps = K >> 5;        // 32-k tiles per segment
    const int T = 3 * tps;

    // A loader: 2 threads/row (128 rows), 32B each. B loader: 1 thread/row (256 rows), 64B.
    const int aRow = tid >> 1;
    const int aOff = (tid & 1) * 32;

    auto issue = [&](int t){
        const int st = t % NSTAGE;
        const int seg = t / tps;
        const int kk  = (t - seg * tps) << 5;   // element offset
        const __nv_bfloat16* Ap = Aseg[seg] + (long)(rowBase + aRow) * K + kk + (aOff >> 1);
        const uint32_t sa = smBase + st * STAGEB + aRow * PITCH + aOff;
        CP_ASYNC16(sa,      Ap);
        CP_ASYNC16(sa + 16, Ap + 8);
        const __nv_bfloat16* Bp = Bseg[seg] + (long)(colBase + tid) * K + kk;
        const uint32_t sb = smBase + st * STAGEB + ATILEB + tid * PITCH;
        CP_ASYNC16(sb,      Bp);
        CP_ASYNC16(sb + 16, Bp + 8);
        CP_ASYNC16(sb + 32, Bp + 16);
        CP_ASYNC16(sb + 48, Bp + 24);
        CP_COMMIT();
    };

    float acc[4][8][4];
    #pragma unroll
    for (int i = 0; i < 4; i++)
        #pragma unroll
        for (int j = 0; j < 8; j++)
            #pragma unroll
            for (int c = 0; c < 4; c++) acc[i][j][c] = 0.f;

    issue(0);
    issue(1);

    // ldmatrix lane address components (stage-invariant)
    const uint32_t aLaneOff = (uint32_t)(warpM*64 + (lane & 15)) * PITCH + ((lane >> 4) & 1) * 16;
    const uint32_t bLaneOff = (uint32_t)(warpN*64 + (lane & 7) + ((lane >> 4) & 1) * 8) * PITCH
                            + ((lane >> 3) & 1) * 16;

    for (int t = 0; t < T; t++) {
        if (t + 1 < T) { CP_WAIT1(); } else { CP_WAIT0(); }
        __syncthreads();
        if (t + 2 < T) issue(t + 2);

        const int st = t % NSTAGE;
        const uint32_t aBase = smBase + st * STAGEB + aLaneOff;
        const uint32_t bBase = smBase + st * STAGEB + ATILEB + bLaneOff;

        #pragma unroll
        for (int ks = 0; ks < 2; ks++) {
            const uint32_t kByte = ks * 32;
            uint32_t afr[4][4];
            #pragma unroll
            for (int mt = 0; mt < 4; mt++)
                ldmatrix_x4(afr[mt][0], afr[mt][1], afr[mt][2], afr[mt][3],
                            aBase + mt * 16 * PITCH + kByte);
            uint32_t bfr[4][4];   // [pair p: n-tiles 2p,2p+1]
            #pragma unroll
            for (int p = 0; p < 4; p++)
                ldmatrix_x4(bfr[p][0], bfr[p][1], bfr[p][2], bfr[p][3],
                            bBase + p * 16 * PITCH + kByte);
            #pragma unroll
            for (int mt = 0; mt < 4; mt++)
                #pragma unroll
                for (int nt = 0; nt < 8; nt++)
                    mma_bf16(acc[mt][nt], afr[mt], &bfr[nt >> 1][(nt & 1) * 2]);
        }
    }

    // ---------------- epilogue (registers -> gmem) ----------------
    #pragma unroll
    for (int mt = 0; mt < 4; mt++) {
        const int r0 = rowBase + warpM*64 + mt*16 + (lane >> 2);
        #pragma unroll
        for (int nt = 0; nt < 8; nt++) {
            const int gc = colBase + warpN*64 + nt*8 + (lane & 3)*2;
            float v00 = acc[mt][nt][0] * alpha;
            float v01 = acc[mt][nt][1] * alpha;
            float v10 = acc[mt][nt][2] * alpha;
            float v11 = acc[mt][nt][3] * alpha;
            if (bias) {
                const float b0 = bias[gc], b1 = bias[gc+1];
                v00 += b0; v01 += b1; v10 += b0; v11 += b1;
            }
            if (MODE == 0) {
                *(float2*)&outF[(long)r0 * N + gc]       = make_float2(v00, v01);
                *(float2*)&outF[(long)(r0+8) * N + gc]   = make_float2(v10, v11);
            } else if (MODE == 1) {
                __nv_bfloat162 h, l;
                split2(v00, h.x, l.x); split2(v01, h.y, l.y);
                *(__nv_bfloat162*)&outHi[(long)r0 * N + gc] = h;
                *(__nv_bfloat162*)&outLo[(long)r0 * N + gc] = l;
                split2(v10, h.x, l.x); split2(v11, h.y, l.y);
                *(__nv_bfloat162*)&outHi[(long)(r0+8) * N + gc] = h;
                *(__nv_bfloat162*)&outLo[(long)(r0+8) * N + gc] = l;
            } else { // MODE 2: v^T per batch [DDIM, NSEQ]
                const int rows[2] = {r0, r0 + 8};
                const float vals[2][2] = {{v00, v01}, {v10, v11}};
                #pragma unroll
                for (int rr = 0; rr < 2; rr++) {
                    const int bb = rows[rr] >> 11, tok = rows[rr] & 2047;
                    const long base = (long)bb * (DDIM * NSEQ) + tok;
                    #pragma unroll
                    for (int cc = 0; cc < 2; cc++) {
                        __nv_bfloat16 h, l; split2(vals[rr][cc], h, l);
                        const long idx = base + (long)(gc + cc) * NSEQ;
                        outHi[idx] = h;
                        outLo[idx] = l;
                    }
                }
            }
        }
    }
}

// ---------------- fp32 -> (bf16 hi, bf16 lo) ----------------
__global__ __launch_bounds__(256)
void split_kernel(const float* __restrict__ x, __nv_bfloat16* __restrict__ hi,
                  __nv_bfloat16* __restrict__ lo, int n4)
{
    const int i = blockIdx.x * blockDim.x + threadIdx.x;
    if (i >= n4) return;
    float4 v = ((const float4*)x)[i];
    __nv_bfloat162 h0, h1, l0, l1;
    split2(v.x, h0.x, l0.x); split2(v.y, h0.y, l0.y);
    split2(v.z, h1.x, l1.x); split2(v.w, h1.y, l1.y);
    ((__nv_bfloat162*)hi)[2*i]   = h0;
    ((__nv_bfloat162*)hi)[2*i+1] = h1;
    ((__nv_bfloat162*)lo)[2*i]   = l0;
    ((__nv_bfloat162*)lo)[2*i+1] = l1;
}

// ---------------- softmax + split (register-resident row, n=2048) ----------------
__global__ __launch_bounds__(256)
void softmax_split_kernel(const float* __restrict__ s, __nv_bfloat16* __restrict__ hi,
                          __nv_bfloat16* __restrict__ lo)
{
    const long rbase = (long)blockIdx.x * NSEQ;
    const float* row = s + rbase;
    const int tid = threadIdx.x;
    const int warp = tid >> 5, lane = tid & 31;
    __shared__ float red[8];

    float4 x0 = ((const float4*)row)[tid];
    float4 x1 = ((const float4*)row)[tid + 256];

    float m = fmaxf(fmaxf(fmaxf(x0.x, x0.y), fmaxf(x0.z, x0.w)),
                    fmaxf(fmaxf(x1.x, x1.y), fmaxf(x1.z, x1.w)));
    #pragma unroll
    for (int o = 16; o > 0; o >>= 1) m = fmaxf(m, __shfl_xor_sync(0xFFFFFFFF, m, o));
    if (lane == 0) red[warp] = m;
    __syncthreads();
    m = red[lane & 7];
    #pragma unroll
    for (int o = 4; o > 0; o >>= 1) m = fmaxf(m, __shfl_xor_sync(0xFFFFFFFF, m, o));

    x0.x = __expf(x0.x - m); x0.y = __expf(x0.y - m);
    x0.z = __expf(x0.z - m); x0.w = __expf(x0.w - m);
    x1.x = __expf(x1.x - m); x1.y = __expf(x1.y - m);
    x1.z = __expf(x1.z - m); x1.w = __expf(x1.w - m);

    float sum = (x0.x + x0.y) + (x0.z + x0.w) + (x1.x + x1.y) + (x1.z + x1.w);
    #pragma unroll
    for (int o = 16; o > 0; o >>= 1) sum += __shfl_xor_sync(0xFFFFFFFF, sum, o);
    __syncthreads();
    if (lane == 0) red[warp] = sum;
    __syncthreads();
    sum = red[lane & 7];
    #pragma unroll
    for (int o = 4; o > 0; o >>= 1) sum += __shfl_xor_sync(0xFFFFFFFF, sum, o);
    const float inv = 1.f / sum;

    __nv_bfloat162 h[4], l[4];
    split2(x0.x * inv, h[0].x, l[0].x); split2(x0.y * inv, h[0].y, l[0].y);
    split2(x0.z * inv, h[1].x, l[1].x); split2(x0.w * inv, h[1].y, l[1].y);
    split2(x1.x * inv, h[2].x, l[2].x); split2(x1.y * inv, h[2].y, l[2].y);
    split2(x1.z * inv, h[3].x, l[3].x); split2(x1.w * inv, h[3].y, l[3].y);

    uint2* hp = (uint2*)(hi + rbase);
    uint2* lp = (uint2*)(lo + rbase);
    uint2 hv0, lv0, hv1, lv1;
    hv0.x = *(uint32_t*)&h[0]; hv0.y = *(uint32_t*)&h[1];
    hv1.x = *(uint32_t*)&h[2]; hv1.y = *(uint32_t*)&h[3];
    lv0.x = *(uint32_t*)&l[0]; lv0.y = *(uint32_t*)&l[1];
    lv1.x = *(uint32_t*)&l[2]; lv1.y = *(uint32_t*)&l[3];
    hp[tid] = hv0; hp[tid + 256] = hv1;
    lp[tid] = lv0; lp[tid + 256] = lv1;
}

// ---------------- launch ----------------
extern "C" void kernel_launch(void* const* d_in, const int* in_sizes, int n_in,
                              void* d_out, int out_size)
{
    (void)in_sizes; (void)n_in; (void)out_size;
    const float* query   = (const float*)d_in[0];
    const float* context = (const float*)d_in[1];
    const float* Wq      = (const float*)d_in[2];
    const float* bq      = (const float*)d_in[3];
    const float* Wv      = (const float*)d_in[4];
    const float* bv      = (const float*)d_in[5];
    const float* Wo      = (const float*)d_in[6];
    const float* bo      = (const float*)d_in[7];
    float* out = (float*)d_out;

    __nv_bfloat16 *qry_hi,*qry_lo,*ctx_hi,*ctx_lo,*wq_hi,*wq_lo,*wv_hi,*wv_lo,*wo_hi,*wo_lo;
    __nv_bfloat16 *q_hi,*q_lo,*vT_hi,*vT_lo,*attn_hi,*attn_lo,*h_hi,*h_lo;
    float* s;
    cudaGetSymbolAddress((void**)&qry_hi, g_qry_hi);  cudaGetSymbolAddress((void**)&qry_lo, g_qry_lo);
    cudaGetSymbolAddress((void**)&ctx_hi, g_ctx_hi);  cudaGetSymbolAddress((void**)&ctx_lo, g_ctx_lo);
    cudaGetSymbolAddress((void**)&wq_hi,  g_wq_hi);   cudaGetSymbolAddress((void**)&wq_lo,  g_wq_lo);
    cudaGetSymbolAddress((void**)&wv_hi,  g_wv_hi);   cudaGetSymbolAddress((void**)&wv_lo,  g_wv_lo);
    cudaGetSymbolAddress((void**)&wo_hi,  g_wo_hi);   cudaGetSymbolAddress((void**)&wo_lo,  g_wo_lo);
    cudaGetSymbolAddress((void**)&q_hi,   g_q_hi);    cudaGetSymbolAddress((void**)&q_lo,   g_q_lo);
    cudaGetSymbolAddress((void**)&vT_hi,  g_vT_hi);   cudaGetSymbolAddress((void**)&vT_lo,  g_vT_lo);
    cudaGetSymbolAddress((void**)&attn_hi,g_attn_hi); cudaGetSymbolAddress((void**)&attn_lo,g_attn_lo);
    cudaGetSymbolAddress((void**)&h_hi,   g_h_hi);    cudaGetSymbolAddress((void**)&h_lo,   g_h_lo);
    cudaGetSymbolAddress((void**)&s,      g_s);

    cudaFuncSetAttribute(mma_gemm<0>, cudaFuncAttributeMaxDynamicSharedMemorySize, SMEM_G);
    cudaFuncSetAttribute(mma_gemm<1>, cudaFuncAttributeMaxDynamicSharedMemorySize, SMEM_G);
    cudaFuncSetAttribute(mma_gemm<2>, cudaFuncAttributeMaxDynamicSharedMemorySize, SMEM_G);

    const float scale = 1.0f / sqrtf((float)DDIM);

    // split inputs
    {
        int n4 = (MFLAT * DDIM) / 4;
        split_kernel<<<(n4 + 255) / 256, 256>>>(query,   qry_hi, qry_lo, n4);
        split_kernel<<<(n4 + 255) / 256, 256>>>(context, ctx_hi, ctx_lo, n4);
        int w4 = (DDIM * DDIM) / 4;
        split_kernel<<<(w4 + 255) / 256, 256>>>(Wq, wq_hi, wq_lo, w4);
        split_kernel<<<(w4 + 255) / 256, 256>>>(Wv, wv_hi, wv_lo, w4);
        split_kernel<<<(w4 + 255) / 256, 256>>>(Wo, wo_hi, wo_lo, w4);
    }

    // 1) q = query @ Wq^T + bq  -> split q
    mma_gemm<1><<<dim3(DDIM/256, MFLAT/128, 1), 256, SMEM_G>>>(
        qry_hi, qry_lo, wq_hi, wq_lo, bq, nullptr, q_hi, q_lo,
        MFLAT, DDIM, DDIM, 1.0f, 0, 0, 0);

    // 2) v = context @ Wv^T + bv -> split v^T (per batch [DDIM, NSEQ])
    mma_gemm<2><<<dim3(DDIM/256, MFLAT/128, 1), 256, SMEM_G>>>(
        ctx_hi, ctx_lo, wv_hi, wv_lo, bv, nullptr, vT_hi, vT_lo,
        MFLAT, DDIM, DDIM, 1.0f, 0, 0, 0);

    // 3) scores = scale * q @ context^T  (batched) -> fp32 s
    mma_gemm<0><<<dim3(NSEQ/256, NSEQ/128, BB), 256, SMEM_G>>>(
        q_hi, q_lo, ctx_hi, ctx_lo, nullptr, s, nullptr, nullptr,
        NSEQ, NSEQ, DDIM, scale,
        (long)NSEQ * DDIM, (long)NSEQ * DDIM, (long)NSEQ * NSEQ);

    // 4) softmax rows -> split attn
    softmax_split_kernel<<<BB * NSEQ, 256>>>(s, attn_hi, attn_lo);

    // 5) h = attn @ v = attn @ (v^T)^T  (batched) -> split h
    mma_gemm<1><<<dim3(DDIM/256, NSEQ/128, BB), 256, SMEM_G>>>(
        attn_hi, attn_lo, vT_hi, vT_lo, nullptr, nullptr, h_hi, h_lo,
        NSEQ, DDIM, NSEQ, 1.0f,
        (long)NSEQ * NSEQ, (long)DDIM * NSEQ, (long)NSEQ * DDIM);

    // 6) out = h @ Wo^T + bo -> fp32
    mma_gemm<0><<<dim3(DDIM/256, MFLAT/128, 1), 256, SMEM_G>>>(
        h_hi, h_lo, wo_hi, wo_lo, bo, out, nullptr, nullptr,
        MFLAT, DDIM, DDIM, 1.0f, 0, 0, 0);
}

// round 9
// speedup vs baseline: 1.9847x; 1.9847x over previous
#include <cuda_runtime.h>
#include <cuda_bf16.h>
#include <cstdint>
#include <math.h>

#define BB 8
#define NSEQ 2048
#define DDIM 512
#define MFLAT (BB*NSEQ)

// ---------------- scratch (device globals: allocation-free) ----------------
__device__ __nv_bfloat16 g_qry_hi[MFLAT*DDIM], g_qry_lo[MFLAT*DDIM];
__device__ __nv_bfloat16 g_ctx_hi[MFLAT*DDIM], g_ctx_lo[MFLAT*DDIM];
__device__ __nv_bfloat16 g_wq_hi[DDIM*DDIM],  g_wq_lo[DDIM*DDIM];
__device__ __nv_bfloat16 g_wv_hi[DDIM*DDIM],  g_wv_lo[DDIM*DDIM];
__device__ __nv_bfloat16 g_wo_hi[DDIM*DDIM],  g_wo_lo[DDIM*DDIM];
__device__ __nv_bfloat16 g_q_hi[MFLAT*DDIM],  g_q_lo[MFLAT*DDIM];
__device__ __nv_bfloat16 g_vT_hi[MFLAT*DDIM], g_vT_lo[MFLAT*DDIM];
__device__ float         g_s[(size_t)BB*NSEQ*NSEQ];
__device__ __nv_bfloat16 g_attn_hi[(size_t)BB*NSEQ*NSEQ], g_attn_lo[(size_t)BB*NSEQ*NSEQ];
__device__ __nv_bfloat16 g_h_hi[MFLAT*DDIM],  g_h_lo[MFLAT*DDIM];

// ---------------- helpers ----------------
__device__ __forceinline__ uint32_t smem_u32(const void* p){
    uint32_t a;
    asm("{ .reg .u64 t; cvta.to.shared.u64 t, %1; cvt.u32.u64 %0, t; }" : "=r"(a) : "l"(p));
    return a;
}
__device__ __forceinline__ void split2(float v, __nv_bfloat16& h, __nv_bfloat16& l){
    h = __float2bfloat16(v);
    l = __float2bfloat16(v - __bfloat162float(h));
}

#define CP_ASYNC16(sm, gm) \
    asm volatile("cp.async.cg.shared.global [%0], [%1], 16;" :: "r"(sm), "l"(gm))
#define CP_COMMIT() asm volatile("cp.async.commit_group;" ::: "memory")
#define CP_WAIT2()  asm volatile("cp.async.wait_group 2;" ::: "memory")
#define CP_WAIT1()  asm volatile("cp.async.wait_group 1;" ::: "memory")
#define CP_WAIT0()  asm volatile("cp.async.wait_group 0;" ::: "memory")

__device__ __forceinline__ void ldmatrix_x4(uint32_t& r0, uint32_t& r1, uint32_t& r2, uint32_t& r3, uint32_t addr){
    asm volatile("ldmatrix.sync.aligned.m8n8.x4.shared.b16 {%0,%1,%2,%3}, [%4];"
        : "=r"(r0), "=r"(r1), "=r"(r2), "=r"(r3) : "r"(addr));
}
__device__ __forceinline__ void mma_bf16(float* c, const uint32_t* a, const uint32_t* b){
    asm volatile(
        "mma.sync.aligned.m16n8k16.row.col.f32.bf16.bf16.f32 "
        "{%0,%1,%2,%3}, {%4,%5,%6,%7}, {%8,%9}, {%0,%1,%2,%3};"
        : "+f"(c[0]), "+f"(c[1]), "+f"(c[2]), "+f"(c[3])
        : "r"(a[0]), "r"(a[1]), "r"(a[2]), "r"(a[3]), "r"(b[0]), "r"(b[1]));
}

// ---------------- GEMM config (CTA 128x128, warp 64x32, BK=32, 4 stages) ----------------
#define PITCH 80
#define TILEB (128*PITCH)          // 10240 B per operand tile
#define STAGEB (2*TILEB)           // 20480 B
#define NSTAGE 4
#define SMEM_G (NSTAGE*STAGEB)     // 81920 B -> 2 CTAs/SM

// Shared mainloop: accumulates 3-segment split-bf16 product into acc[4][4][4].
// One __syncthreads per iteration; tail-aware cp.async waits.
#define GEMM_MAINLOOP(Aseg, Bseg, Kdim)                                              \
    const int tps = (Kdim) >> 5;                                                     \
    const int T = 3 * tps;                                                           \
    const int ldRow = tid >> 1;                                                      \
    const int ldOff = (tid & 1) * 32;                                                \
    auto issue = [&](int t){                                                         \
        const int st = t & 3;                                                        \
        const int seg = t / tps;                                                     \
        const int kk  = (t - seg * tps) << 5;                                        \
        const __nv_bfloat16* Ap = Aseg[seg] + (long)(rowBase + ldRow) * (Kdim) + kk + (ldOff >> 1); \
        const __nv_bfloat16* Bp = Bseg[seg] + (long)(colBase + ldRow) * (Kdim) + kk + (ldOff >> 1); \
        const uint32_t sa = smBase + st * STAGEB + ldRow * PITCH + ldOff;            \
        const uint32_t sb = sa + TILEB;                                              \
        CP_ASYNC16(sa,      Ap);                                                     \
        CP_ASYNC16(sa + 16, Ap + 8);                                                 \
        CP_ASYNC16(sb,      Bp);                                                     \
        CP_ASYNC16(sb + 16, Bp + 8);                                                 \
        CP_COMMIT();                                                                 \
    };                                                                               \
    issue(0); issue(1); issue(2);                                                    \
    const uint32_t aLaneOff = (uint32_t)(warpM*64 + (lane & 15)) * PITCH + ((lane >> 4) & 1) * 16; \
    const uint32_t bLaneOff = (uint32_t)(warpN*32 + (lane & 7) + ((lane >> 4) & 1) * 8) * PITCH    \
                            + ((lane >> 3) & 1) * 16;                                \
    for (int t = 0; t < T; t++) {                                                    \
        const int rem = T - 1 - t;                                                   \
        if (rem >= 2) { CP_WAIT2(); } else if (rem == 1) { CP_WAIT1(); } else { CP_WAIT0(); } \
        __syncthreads();                                                             \
        if (t + 3 < T) issue(t + 3);                                                 \
        const int st = t & 3;                                                        \
        const uint32_t aBase = smBase + st * STAGEB + aLaneOff;                      \
        const uint32_t bBase = smBase + st * STAGEB + TILEB + bLaneOff;              \
        _Pragma("unroll")                                                            \
        for (int ks = 0; ks < 2; ks++) {                                             \
            const uint32_t kByte = ks * 32;                                          \
            uint32_t afr[4][4];                                                      \
            _Pragma("unroll")                                                        \
            for (int mt = 0; mt < 4; mt++)                                           \
                ldmatrix_x4(afr[mt][0], afr[mt][1], afr[mt][2], afr[mt][3],          \
                            aBase + mt * 16 * PITCH + kByte);                        \
            uint32_t bfr[2][4];                                                      \
            _Pragma("unroll")                                                        \
            for (int p = 0; p < 2; p++)                                              \
                ldmatrix_x4(bfr[p][0], bfr[p][1], bfr[p][2], bfr[p][3],              \
                            bBase + p * 16 * PITCH + kByte);                         \
            _Pragma("unroll")                                                        \
            for (int mt = 0; mt < 4; mt++)                                           \
                _Pragma("unroll")                                                    \
                for (int nt = 0; nt < 4; nt++)                                       \
                    mma_bf16(acc[mt][nt], afr[mt], &bfr[nt >> 1][(nt & 1) * 2]);     \
        }                                                                            \
    }

// ---------------- generic GEMM (modes 0: fp32+bias, 1: split bf16) ----------------
template<int MODE>
__global__ __launch_bounds__(256, 2)
void mma_gemm(const __nv_bfloat16* __restrict__ Ahi, const __nv_bfloat16* __restrict__ Alo,
              const __nv_bfloat16* __restrict__ Bhi, const __nv_bfloat16* __restrict__ Blo,
              const float* __restrict__ bias,
              float* __restrict__ outF, __nv_bfloat16* __restrict__ outHi, __nv_bfloat16* __restrict__ outLo,
              int M, int N, int K, float alpha,
              long sA, long sB, long sC)
{
    extern __shared__ __align__(128) char smem[];
    const int tid  = threadIdx.x;
    const int warp = tid >> 5;
    const int lane = tid & 31;
    const int warpM = warp >> 2;
    const int warpN = warp & 3;

    const int z = blockIdx.z;
    Ahi += (long)z * sA;  Alo += (long)z * sA;
    Bhi += (long)z * sB;  Blo += (long)z * sB;
    if (MODE == 0) { outF += (long)z * sC; }
    else { outHi += (long)z * sC; outLo += (long)z * sC; }

    const int rowBase = blockIdx.y * 128;
    const int colBase = blockIdx.x * 128;
    const uint32_t smBase = smem_u32(smem);

    const __nv_bfloat16* Aseg[3] = {Ahi, Ahi, Alo};
    const __nv_bfloat16* Bseg[3] = {Bhi, Blo, Bhi};

    float acc[4][4][4];
    #pragma unroll
    for (int i = 0; i < 4; i++)
        #pragma unroll
        for (int j = 0; j < 4; j++)
            #pragma unroll
            for (int c = 0; c < 4; c++) acc[i][j][c] = 0.f;

    GEMM_MAINLOOP(Aseg, Bseg, K)

    #pragma unroll
    for (int mt = 0; mt < 4; mt++) {
        const int r0 = rowBase + warpM*64 + mt*16 + (lane >> 2);
        #pragma unroll
        for (int nt = 0; nt < 4; nt++) {
            const int gc = colBase + warpN*32 + nt*8 + (lane & 3)*2;
            float v00 = acc[mt][nt][0] * alpha;
            float v01 = acc[mt][nt][1] * alpha;
            float v10 = acc[mt][nt][2] * alpha;
            float v11 = acc[mt][nt][3] * alpha;
            if (bias) {
                const float b0 = bias[gc], b1 = bias[gc+1];
                v00 += b0; v01 += b1; v10 += b0; v11 += b1;
            }
            if (MODE == 0) {
                *(float2*)&outF[(long)r0 * N + gc]       = make_float2(v00, v01);
                *(float2*)&outF[(long)(r0+8) * N + gc]   = make_float2(v10, v11);
            } else {
                __nv_bfloat162 h, l;
                split2(v00, h.x, l.x); split2(v01, h.y, l.y);
                *(__nv_bfloat162*)&outHi[(long)r0 * N + gc] = h;
                *(__nv_bfloat162*)&outLo[(long)r0 * N + gc] = l;
                split2(v10, h.x, l.x); split2(v11, h.y, l.y);
                *(__nv_bfloat162*)&outHi[(long)(r0+8) * N + gc] = h;
                *(__nv_bfloat162*)&outLo[(long)(r0+8) * N + gc] = l;
            }
        }
    }
}

// ---------------- combined Q/V projection (grid.z: 0 = q-proj, 1 = v-proj^T) ----------------
__global__ __launch_bounds__(256, 2)
void qv_gemm(const __nv_bfloat16* __restrict__ qryh, const __nv_bfloat16* __restrict__ qryl,
             const __nv_bfloat16* __restrict__ wqh,  const __nv_bfloat16* __restrict__ wql,
             const float* __restrict__ bq,
             __nv_bfloat16* __restrict__ qh, __nv_bfloat16* __restrict__ ql,
             const __nv_bfloat16* __restrict__ ctxh, const __nv_bfloat16* __restrict__ ctxl,
             const __nv_bfloat16* __restrict__ wvh,  const __nv_bfloat16* __restrict__ wvl,
             const float* __restrict__ bv,
             __nv_bfloat16* __restrict__ vth, __nv_bfloat16* __restrict__ vtl)
{
    extern __shared__ __align__(128) char smem[];
    const int tid  = threadIdx.x;
    const int warp = tid >> 5;
    const int lane = tid & 31;
    const int warpM = warp >> 2;
    const int warpN = warp & 3;
    const int isV = blockIdx.z;

    const int rowBase = blockIdx.y * 128;
    const int colBase = blockIdx.x * 128;
    const uint32_t smBase = smem_u32(smem);

    const __nv_bfloat16* Ahi = isV ? ctxh : qryh;
    const __nv_bfloat16* Alo = isV ? ctxl : qryl;
    const __nv_bfloat16* Bhi = isV ? wvh  : wqh;
    const __nv_bfloat16* Blo = isV ? wvl  : wql;
    const float* bias        = isV ? bv   : bq;

    const __nv_bfloat16* Aseg[3] = {Ahi, Ahi, Alo};
    const __nv_bfloat16* Bseg[3] = {Bhi, Blo, Bhi};

    float acc[4][4][4];
    #pragma unroll
    for (int i = 0; i < 4; i++)
        #pragma unroll
        for (int j = 0; j < 4; j++)
            #pragma unroll
            for (int c = 0; c < 4; c++) acc[i][j][c] = 0.f;

    GEMM_MAINLOOP(Aseg, Bseg, DDIM)

    #pragma unroll
    for (int mt = 0; mt < 4; mt++) {
        const int r0 = rowBase + warpM*64 + mt*16 + (lane >> 2);
        #pragma unroll
        for (int nt = 0; nt < 4; nt++) {
            const int gc = colBase + warpN*32 + nt*8 + (lane & 3)*2;
            const float b0 = bias[gc], b1 = bias[gc+1];
            float v00 = acc[mt][nt][0] + b0;
            float v01 = acc[mt][nt][1] + b1;
            float v10 = acc[mt][nt][2] + b0;
            float v11 = acc[mt][nt][3] + b1;
            if (!isV) {
                __nv_bfloat162 h, l;
                split2(v00, h.x, l.x); split2(v01, h.y, l.y);
                *(__nv_bfloat162*)&qh[(long)r0 * DDIM + gc] = h;
                *(__nv_bfloat162*)&ql[(long)r0 * DDIM + gc] = l;
                split2(v10, h.x, l.x); split2(v11, h.y, l.y);
                *(__nv_bfloat162*)&qh[(long)(r0+8) * DDIM + gc] = h;
                *(__nv_bfloat162*)&ql[(long)(r0+8) * DDIM + gc] = l;
            } else { // v^T per batch [DDIM, NSEQ]
                const int rows[2] = {r0, r0 + 8};
                const float vals[2][2] = {{v00, v01}, {v10, v11}};
                #pragma unroll
                for (int rr = 0; rr < 2; rr++) {
                    const int bb = rows[rr] >> 11, tok = rows[rr] & 2047;
                    const long base = (long)bb * (DDIM * NSEQ) + tok;
                    #pragma unroll
                    for (int cc = 0; cc < 2; cc++) {
                        __nv_bfloat16 h, l; split2(vals[rr][cc], h, l);
                        const long idx = base + (long)(gc + cc) * NSEQ;
                        vth[idx] = h;
                        vtl[idx] = l;
                    }
                }
            }
        }
    }
}

// ---------------- fused input split: query, context, Wq, Wv, Wo ----------------
#define NQ4 ((MFLAT*DDIM)/4)
#define NW4 ((DDIM*DDIM)/4)
__global__ __launch_bounds__(256)
void split_all_kernel(const float* __restrict__ query, const float* __restrict__ context,
                      const float* __restrict__ Wq, const float* __restrict__ Wv, const float* __restrict__ Wo,
                      __nv_bfloat16* __restrict__ qryh, __nv_bfloat16* __restrict__ qryl,
                      __nv_bfloat16* __restrict__ ctxh, __nv_bfloat16* __restrict__ ctxl,
                      __nv_bfloat16* __restrict__ wqh,  __nv_bfloat16* __restrict__ wql,
                      __nv_bfloat16* __restrict__ wvh,  __nv_bfloat16* __restrict__ wvl,
                      __nv_bfloat16* __restrict__ woh,  __nv_bfloat16* __restrict__ wol)
{
    int i = blockIdx.x * blockDim.x + threadIdx.x;
    const float* src; __nv_bfloat16 *hi, *lo;
    if (i < NQ4)                  { src = query;   hi = qryh; lo = qryl; }
    else if ((i -= NQ4) < NQ4)    { src = context; hi = ctxh; lo = ctxl; }
    else if ((i -= NQ4) < NW4)    { src = Wq;      hi = wqh;  lo = wql;  }
    else if ((i -= NW4) < NW4)    { src = Wv;      hi = wvh;  lo = wvl;  }
    else if ((i -= NW4) < NW4)    { src = Wo;      hi = woh;  lo = wol;  }
    else return;
    float4 v = ((const float4*)src)[i];
    __nv_bfloat162 h0, h1, l0, l1;
    split2(v.x, h0.x, l0.x); split2(v.y, h0.y, l0.y);
    split2(v.z, h1.x, l1.x); split2(v.w, h1.y, l1.y);
    ((__nv_bfloat162*)hi)[2*i]   = h0;
    ((__nv_bfloat162*)hi)[2*i+1] = h1;
    ((__nv_bfloat162*)lo)[2*i]   = l0;
    ((__nv_bfloat162*)lo)[2*i+1] = l1;
}

// ---------------- softmax + split (register-resident row, n=2048) ----------------
__global__ __launch_bounds__(256)
void softmax_split_kernel(const float* __restrict__ s, __nv_bfloat16* __restrict__ hi,
                          __nv_bfloat16* __restrict__ lo)
{
    const long rbase = (long)blockIdx.x * NSEQ;
    const float* row = s + rbase;
    const int tid = threadIdx.x;
    const int warp = tid >> 5, lane = tid & 31;
    __shared__ float red[8];

    float4 x0 = ((const float4*)row)[tid];
    float4 x1 = ((const float4*)row)[tid + 256];

    float m = fmaxf(fmaxf(fmaxf(x0.x, x0.y), fmaxf(x0.z, x0.w)),
                    fmaxf(fmaxf(x1.x, x1.y), fmaxf(x1.z, x1.w)));
    #pragma unroll
    for (int o = 16; o > 0; o >>= 1) m = fmaxf(m, __shfl_xor_sync(0xFFFFFFFF, m, o));
    if (lane == 0) red[warp] = m;
    __syncthreads();
    m = red[lane & 7];
    #pragma unroll
    for (int o = 4; o > 0; o >>= 1) m = fmaxf(m, __shfl_xor_sync(0xFFFFFFFF, m, o));

    x0.x = __expf(x0.x - m); x0.y = __expf(x0.y - m);
    x0.z = __expf(x0.z - m); x0.w = __expf(x0.w - m);
    x1.x = __expf(x1.x - m); x1.y = __expf(x1.y - m);
    x1.z = __expf(x1.z - m); x1.w = __expf(x1.w - m);

    float sum = (x0.x + x0.y) + (x0.z + x0.w) + (x1.x + x1.y) + (x1.z + x1.w);
    #pragma unroll
    for (int o = 16; o > 0; o >>= 1) sum += __shfl_xor_sync(0xFFFFFFFF, sum, o);
    __syncthreads();
    if (lane == 0) red[warp] = sum;
    __syncthreads();
    sum = red[lane & 7];
    #pragma unroll
    for (int o = 4; o > 0; o >>= 1) sum += __shfl_xor_sync(0xFFFFFFFF, sum, o);
    const float inv = 1.f / sum;

    __nv_bfloat162 h[4], l[4];
    split2(x0.x * inv, h[0].x, l[0].x); split2(x0.y * inv, h[0].y, l[0].y);
    split2(x0.z * inv, h[1].x, l[1].x); split2(x0.w * inv, h[1].y, l[1].y);
    split2(x1.x * inv, h[2].x, l[2].x); split2(x1.y * inv, h[2].y, l[2].y);
    split2(x1.z * inv, h[3].x, l[3].x); split2(x1.w * inv, h[3].y, l[3].y);

    uint2* hp = (uint2*)(hi + rbase);
    uint2* lp = (uint2*)(lo + rbase);
    uint2 hv0, lv0, hv1, lv1;
    hv0.x = *(uint32_t*)&h[0]; hv0.y = *(uint32_t*)&h[1];
    hv1.x = *(uint32_t*)&h[2]; hv1.y = *(uint32_t*)&h[3];
    lv0.x = *(uint32_t*)&l[0]; lv0.y = *(uint32_t*)&l[1];
    lv1.x = *(uint32_t*)&l[2]; lv1.y = *(uint32_t*)&l[3];
    hp[tid] = hv0; hp[tid + 256] = hv1;
    lp[tid] = lv0; lp[tid + 256] = lv1;
}

// ---------------- launch ----------------
extern "C" void kernel_launch(void* const* d_in, const int* in_sizes, int n_in,
                              void* d_out, int out_size)
{
    (void)in_sizes; (void)n_in; (void)out_size;
    const float* query   = (const float*)d_in[0];
    const float* context = (const float*)d_in[1];
    const float* Wq      = (const float*)d_in[2];
    const float* bq      = (const float*)d_in[3];
    const float* Wv      = (const float*)d_in[4];
    const float* bv      = (const float*)d_in[5];
    const float* Wo      = (const float*)d_in[6];
    const float* bo      = (const float*)d_in[7];
    float* out = (float*)d_out;

    __nv_bfloat16 *qry_hi,*qry_lo,*ctx_hi,*ctx_lo,*wq_hi,*wq_lo,*wv_hi,*wv_lo,*wo_hi,*wo_lo;
    __nv_bfloat16 *q_hi,*q_lo,*vT_hi,*vT_lo,*attn_hi,*attn_lo,*h_hi,*h_lo;
    float* s;
    cudaGetSymbolAddress((void**)&qry_hi, g_qry_hi);  cudaGetSymbolAddress((void**)&qry_lo, g_qry_lo);
    cudaGetSymbolAddress((void**)&ctx_hi, g_ctx_hi);  cudaGetSymbolAddress((void**)&ctx_lo, g_ctx_lo);
    cudaGetSymbolAddress((void**)&wq_hi,  g_wq_hi);   cudaGetSymbolAddress((void**)&wq_lo,  g_wq_lo);
    cudaGetSymbolAddress((void**)&wv_hi,  g_wv_hi);   cudaGetSymbolAddress((void**)&wv_lo,  g_wv_lo);
    cudaGetSymbolAddress((void**)&wo_hi,  g_wo_hi);   cudaGetSymbolAddress((void**)&wo_lo,  g_wo_lo);
    cudaGetSymbolAddress((void**)&q_hi,   g_q_hi);    cudaGetSymbolAddress((void**)&q_lo,   g_q_lo);
    cudaGetSymbolAddress((void**)&vT_hi,  g_vT_hi);   cudaGetSymbolAddress((void**)&vT_lo,  g_vT_lo);
    cudaGetSymbolAddress((void**)&attn_hi,g_attn_hi); cudaGetSymbolAddress((void**)&attn_lo,g_attn_lo);
    cudaGetSymbolAddress((void**)&h_hi,   g_h_hi);    cudaGetSymbolAddress((void**)&h_lo,   g_h_lo);
    cudaGetSymbolAddress((void**)&s,      g_s);

    cudaFuncSetAttribute(mma_gemm<0>, cudaFuncAttributeMaxDynamicSharedMemorySize, SMEM_G);
    cudaFuncSetAttribute(mma_gemm<1>, cudaFuncAttributeMaxDynamicSharedMemorySize, SMEM_G);
    cudaFuncSetAttribute(qv_gemm,     cudaFuncAttributeMaxDynamicSharedMemorySize, SMEM_G);

    const float scale = 1.0f / sqrtf((float)DDIM);

    // 0) split all fp32 inputs -> bf16 hi/lo (one launch)
    {
        int total = 2 * NQ4 + 3 * NW4;
        split_all_kernel<<<(total + 255) / 256, 256>>>(
            query, context, Wq, Wv, Wo,
            qry_hi, qry_lo, ctx_hi, ctx_lo,
            wq_hi, wq_lo, wv_hi, wv_lo, wo_hi, wo_lo);
    }

    // 1+2) q = query@Wq^T + bq  AND  v^T = (context@Wv^T + bv)^T  (one launch, z=2)
    qv_gemm<<<dim3(DDIM/128, MFLAT/128, 2), 256, SMEM_G>>>(
        qry_hi, qry_lo, wq_hi, wq_lo, bq, q_hi, q_lo,
        ctx_hi, ctx_lo, wv_hi, wv_lo, bv, vT_hi, vT_lo);

    // 3) scores = scale * q @ context^T  (batched) -> fp32 s
    mma_gemm<0><<<dim3(NSEQ/128, NSEQ/128, BB), 256, SMEM_G>>>(
        q_hi, q_lo, ctx_hi, ctx_lo, nullptr, s, nullptr, nullptr,
        NSEQ, NSEQ, DDIM, scale,
        (long)NSEQ * DDIM, (long)NSEQ * DDIM, (long)NSEQ * NSEQ);

    // 4) softmax rows -> split attn
    softmax_split_kernel<<<BB * NSEQ, 256>>>(s, attn_hi, attn_lo);

    // 5) h = attn @ v = attn @ (v^T)^T  (batched) -> split h
    mma_gemm<1><<<dim3(DDIM/128, NSEQ/128, BB), 256, SMEM_G>>>(
        attn_hi, attn_lo, vT_hi, vT_lo, nullptr, nullptr, h_hi, h_lo,
        NSEQ, DDIM, NSEQ, 1.0f,
        (long)NSEQ * NSEQ, (long)DDIM * NSEQ, (long)NSEQ * DDIM);

    // 6) out = h @ Wo^T + bo -> fp32
    mma_gemm<0><<<dim3(DDIM/128, MFLAT/128, 1), 256, SMEM_G>>>(
        h_hi, h_lo, wo_hi, wo_lo, bo, out, nullptr, nullptr,
        MFLAT, DDIM, DDIM, 1.0f, 0, 0, 0);
}

// round 10
// speedup vs baseline: 2.8350x; 1.4284x over previous
#include <cuda_runtime.h>
#include <cuda_fp16.h>
#include <cstdint>
#include <math.h>

#define BB 8
#define NSEQ 2048
#define DDIM 512
#define MFLAT (BB*NSEQ)

// ---------------- scratch (device globals: allocation-free) ----------------
__device__ __half g_qry_hi[MFLAT*DDIM], g_qry_lo[MFLAT*DDIM];
__device__ __half g_ctx_hi[MFLAT*DDIM], g_ctx_lo[MFLAT*DDIM];
__device__ __half g_wq[DDIM*DDIM], g_wv[DDIM*DDIM], g_wo[DDIM*DDIM];   // rounded B operands
__device__ __half g_q_hi[MFLAT*DDIM],  g_q_lo[MFLAT*DDIM];
__device__ __half g_vT[MFLAT*DDIM];                                    // rounded, transposed per batch
__device__ float  g_s[(size_t)BB*NSEQ*NSEQ];
__device__ __half g_attn_hi[(size_t)BB*NSEQ*NSEQ], g_attn_lo[(size_t)BB*NSEQ*NSEQ];
__device__ __half g_h_hi[MFLAT*DDIM],  g_h_lo[MFLAT*DDIM];

// ---------------- helpers ----------------
__device__ __forceinline__ uint32_t smem_u32(const void* p){
    uint32_t a;
    asm("{ .reg .u64 t; cvta.to.shared.u64 t, %1; cvt.u32.u64 %0, t; }" : "=r"(a) : "l"(p));
    return a;
}
__device__ __forceinline__ void split2h(float v, __half& h, __half& l){
    h = __float2half(v);
    l = __float2half(v - __half2float(h));
}

#define CP_ASYNC16(sm, gm) \
    asm volatile("cp.async.cg.shared.global [%0], [%1], 16;" :: "r"(sm), "l"(gm))
#define CP_COMMIT() asm volatile("cp.async.commit_group;" ::: "memory")
#define CP_WAIT2()  asm volatile("cp.async.wait_group 2;" ::: "memory")
#define CP_WAIT1()  asm volatile("cp.async.wait_group 1;" ::: "memory")
#define CP_WAIT0()  asm volatile("cp.async.wait_group 0;" ::: "memory")

__device__ __forceinline__ void ldmatrix_x4(uint32_t& r0, uint32_t& r1, uint32_t& r2, uint32_t& r3, uint32_t addr){
    asm volatile("ldmatrix.sync.aligned.m8n8.x4.shared.b16 {%0,%1,%2,%3}, [%4];"
        : "=r"(r0), "=r"(r1), "=r"(r2), "=r"(r3) : "r"(addr));
}
__device__ __forceinline__ void mma_f16(float* c, const uint32_t* a, const uint32_t* b){
    asm volatile(
        "mma.sync.aligned.m16n8k16.row.col.f32.f16.f16.f32 "
        "{%0,%1,%2,%3}, {%4,%5,%6,%7}, {%8,%9}, {%0,%1,%2,%3};"
        : "+f"(c[0]), "+f"(c[1]), "+f"(c[2]), "+f"(c[3])
        : "r"(a[0]), "r"(a[1]), "r"(a[2]), "r"(a[3]), "r"(b[0]), "r"(b[1]));
}

// ---------------- GEMM config (CTA 128x128, warp 64x32, BK=32, 4 stages) ----------------
#define PITCH 80
#define TILEB (128*PITCH)
#define STAGEB (2*TILEB)
#define NSTAGE 4
#define SMEM_G (NSTAGE*STAGEB)     // 81920 B -> 2 CTAs/SM

// Mainloop: acc += (Ah + Al) @ B^T over 2 segments. One __syncthreads per iter.
#define GEMM_MAINLOOP(Aseg, Bop, Kdim)                                               \
    const int tps = (Kdim) >> 5;                                                     \
    const int T = 2 * tps;                                                           \
    const int ldRow = tid >> 1;                                                      \
    const int ldOff = (tid & 1) * 32;                                                \
    auto issue = [&](int t){                                                         \
        const int st = t & 3;                                                        \
        const int seg = t / tps;                                                     \
        const int kk  = (t - seg * tps) << 5;                                        \
        const __half* Ap = Aseg[seg] + (long)(rowBase + ldRow) * (Kdim) + kk + (ldOff >> 1); \
        const __half* Bp = (Bop) + (long)(colBase + ldRow) * (Kdim) + kk + (ldOff >> 1);     \
        const uint32_t sa = smBase + st * STAGEB + ldRow * PITCH + ldOff;            \
        const uint32_t sb = sa + TILEB;                                              \
        CP_ASYNC16(sa,      Ap);                                                     \
        CP_ASYNC16(sa + 16, Ap + 8);                                                 \
        CP_ASYNC16(sb,      Bp);                                                     \
        CP_ASYNC16(sb + 16, Bp + 8);                                                 \
        CP_COMMIT();                                                                 \
    };                                                                               \
    issue(0); issue(1); issue(2);                                                    \
    const uint32_t aLaneOff = (uint32_t)(warpM*64 + (lane & 15)) * PITCH + ((lane >> 4) & 1) * 16; \
    const uint32_t bLaneOff = (uint32_t)(warpN*32 + (lane & 7) + ((lane >> 4) & 1) * 8) * PITCH    \
                            + ((lane >> 3) & 1) * 16;                                \
    for (int t = 0; t < T; t++) {                                                    \
        const int rem = T - 1 - t;                                                   \
        if (rem >= 2) { CP_WAIT2(); } else if (rem == 1) { CP_WAIT1(); } else { CP_WAIT0(); } \
        __syncthreads();                                                             \
        if (t + 3 < T) issue(t + 3);                                                 \
        const int st = t & 3;                                                        \
        const uint32_t aBase = smBase + st * STAGEB + aLaneOff;                      \
        const uint32_t bBase = smBase + st * STAGEB + TILEB + bLaneOff;              \
        _Pragma("unroll")                                                            \
        for (int ks = 0; ks < 2; ks++) {                                             \
            const uint32_t kByte = ks * 32;                                          \
            uint32_t afr[4][4];                                                      \
            _Pragma("unroll")                                                        \
            for (int mt = 0; mt < 4; mt++)                                           \
                ldmatrix_x4(afr[mt][0], afr[mt][1], afr[mt][2], afr[mt][3],          \
                            aBase + mt * 16 * PITCH + kByte);                        \
            uint32_t bfr[2][4];                                                      \
            _Pragma("unroll")                                                        \
            for (int p = 0; p < 2; p++)                                              \
                ldmatrix_x4(bfr[p][0], bfr[p][1], bfr[p][2], bfr[p][3],              \
                            bBase + p * 16 * PITCH + kByte);                         \
            _Pragma("unroll")                                                        \
            for (int mt = 0; mt < 4; mt++)                                           \
                _Pragma("unroll")                                                    \
                for (int nt = 0; nt < 4; nt++)                                       \
                    mma_f16(acc[mt][nt], afr[mt], &bfr[nt >> 1][(nt & 1) * 2]);      \
        }                                                                            \
    }

// ---------------- generic GEMM (MODE 0: fp32 out (+bias), MODE 1: split fp16 out) ----------------
template<int MODE>
__global__ __launch_bounds__(256, 2)
void mma_gemm(const __half* __restrict__ Ahi, const __half* __restrict__ Alo,
              const __half* __restrict__ B,
              const float* __restrict__ bias,
              float* __restrict__ outF, __half* __restrict__ outHi, __half* __restrict__ outLo,
              int M, int N, int K, float alpha,
              long sA, long sB, long sC)
{
    extern __shared__ __align__(128) char smem[];
    const int tid  = threadIdx.x;
    const int warp = tid >> 5;
    const int lane = tid & 31;
    const int warpM = warp >> 2;
    const int warpN = warp & 3;

    const int z = blockIdx.z;
    Ahi += (long)z * sA;  Alo += (long)z * sA;
    B   += (long)z * sB;
    if (MODE == 0) { outF += (long)z * sC; }
    else { outHi += (long)z * sC; outLo += (long)z * sC; }

    const int rowBase = blockIdx.y * 128;
    const int colBase = blockIdx.x * 128;
    const uint32_t smBase = smem_u32(smem);

    const __half* Aseg[2] = {Ahi, Alo};

    float acc[4][4][4];
    #pragma unroll
    for (int i = 0; i < 4; i++)
        #pragma unroll
        for (int j = 0; j < 4; j++)
            #pragma unroll
            for (int c = 0; c < 4; c++) acc[i][j][c] = 0.f;

    GEMM_MAINLOOP(Aseg, B, K)

    #pragma unroll
    for (int mt = 0; mt < 4; mt++) {
        const int r0 = rowBase + warpM*64 + mt*16 + (lane >> 2);
        #pragma unroll
        for (int nt = 0; nt < 4; nt++) {
            const int gc = colBase + warpN*32 + nt*8 + (lane & 3)*2;
            float v00 = acc[mt][nt][0] * alpha;
            float v01 = acc[mt][nt][1] * alpha;
            float v10 = acc[mt][nt][2] * alpha;
            float v11 = acc[mt][nt][3] * alpha;
            if (bias) {
                const float b0 = bias[gc], b1 = bias[gc+1];
                v00 += b0; v01 += b1; v10 += b0; v11 += b1;
            }
            if (MODE == 0) {
                *(float2*)&outF[(long)r0 * N + gc]       = make_float2(v00, v01);
                *(float2*)&outF[(long)(r0+8) * N + gc]   = make_float2(v10, v11);
            } else {
                __half2 h, l;
                split2h(v00, h.x, l.x); split2h(v01, h.y, l.y);
                *(__half2*)&outHi[(long)r0 * N + gc] = h;
                *(__half2*)&outLo[(long)r0 * N + gc] = l;
                split2h(v10, h.x, l.x); split2h(v11, h.y, l.y);
                *(__half2*)&outHi[(long)(r0+8) * N + gc] = h;
                *(__half2*)&outLo[(long)(r0+8) * N + gc] = l;
            }
        }
    }
}

// ---------------- combined Q/V projection (z=0: q-proj split out, z=1: v-proj^T rounded out) ----
__global__ __launch_bounds__(256, 2)
void qv_gemm(const __half* __restrict__ qryh, const __half* __restrict__ qryl,
             const __half* __restrict__ wq, const float* __restrict__ bq,
             __half* __restrict__ qh, __half* __restrict__ ql,
             const __half* __restrict__ ctxh, const __half* __restrict__ ctxl,
             const __half* __restrict__ wv, const float* __restrict__ bv,
             __half* __restrict__ vt)
{
    extern __shared__ __align__(128) char smem[];
    const int tid  = threadIdx.x;
    const int warp = tid >> 5;
    const int lane = tid & 31;
    const int warpM = warp >> 2;
    const int warpN = warp & 3;
    const int isV = blockIdx.z;

    const int rowBase = blockIdx.y * 128;
    const int colBase = blockIdx.x * 128;
    const uint32_t smBase = smem_u32(smem);

    const __half* Aseg[2];
    Aseg[0] = isV ? ctxh : qryh;
    Aseg[1] = isV ? ctxl : qryl;
    const __half* B   = isV ? wv : wq;
    const float* bias = isV ? bv : bq;

    float acc[4][4][4];
    #pragma unroll
    for (int i = 0; i < 4; i++)
        #pragma unroll
        for (int j = 0; j < 4; j++)
            #pragma unroll
            for (int c = 0; c < 4; c++) acc[i][j][c] = 0.f;

    GEMM_MAINLOOP(Aseg, B, DDIM)

    #pragma unroll
    for (int mt = 0; mt < 4; mt++) {
        const int r0 = rowBase + warpM*64 + mt*16 + (lane >> 2);
        #pragma unroll
        for (int nt = 0; nt < 4; nt++) {
            const int gc = colBase + warpN*32 + nt*8 + (lane & 3)*2;
            const float b0 = bias[gc], b1 = bias[gc+1];
            float v00 = acc[mt][nt][0] + b0;
            float v01 = acc[mt][nt][1] + b1;
            float v10 = acc[mt][nt][2] + b0;
            float v11 = acc[mt][nt][3] + b1;
            if (!isV) {
                __half2 h, l;
                split2h(v00, h.x, l.x); split2h(v01, h.y, l.y);
                *(__half2*)&qh[(long)r0 * DDIM + gc] = h;
                *(__half2*)&ql[(long)r0 * DDIM + gc] = l;
                split2h(v10, h.x, l.x); split2h(v11, h.y, l.y);
                *(__half2*)&qh[(long)(r0+8) * DDIM + gc] = h;
                *(__half2*)&ql[(long)(r0+8) * DDIM + gc] = l;
            } else { // v^T per batch [DDIM, NSEQ], rounded single fp16
                const int rows[2] = {r0, r0 + 8};
                const float vals[2][2] = {{v00, v01}, {v10, v11}};
                #pragma unroll
                for (int rr = 0; rr < 2; rr++) {
                    const int bb = rows[rr] >> 11, tok = rows[rr] & 2047;
                    const long base = (long)bb * (DDIM * NSEQ) + tok;
                    #pragma unroll
                    for (int cc = 0; cc < 2; cc++)
                        vt[base + (long)(gc + cc) * NSEQ] = __float2half(vals[rr][cc]);
                }
            }
        }
    }
}

// ---------------- fused input split/round ----------------
#define NQ4 ((MFLAT*DDIM)/4)
#define NW4 ((DDIM*DDIM)/4)
__global__ __launch_bounds__(256)
void split_all_kernel(const float* __restrict__ query, const float* __restrict__ context,
                      const float* __restrict__ Wq, const float* __restrict__ Wv, const float* __restrict__ Wo,
                      __half* __restrict__ qryh, __half* __restrict__ qryl,
                      __half* __restrict__ ctxh, __half* __restrict__ ctxl,
                      __half* __restrict__ wq, __half* __restrict__ wv, __half* __restrict__ wo)
{
    int i = blockIdx.x * blockDim.x + threadIdx.x;
    const float* src; __half *hi, *lo = nullptr;
    if (i < NQ4)                  { src = query;   hi = qryh; lo = qryl; }
    else if ((i -= NQ4) < NQ4)    { src = context; hi = ctxh; lo = ctxl; }
    else if ((i -= NQ4) < NW4)    { src = Wq;      hi = wq; }
    else if ((i -= NW4) < NW4)    { src = Wv;      hi = wv; }
    else if ((i -= NW4) < NW4)    { src = Wo;      hi = wo; }
    else return;
    float4 v = ((const float4*)src)[i];
    if (lo) {
        __half2 h0, h1, l0, l1;
        split2h(v.x, h0.x, l0.x); split2h(v.y, h0.y, l0.y);
        split2h(v.z, h1.x, l1.x); split2h(v.w, h1.y, l1.y);
        ((__half2*)hi)[2*i]   = h0;
        ((__half2*)hi)[2*i+1] = h1;
        ((__half2*)lo)[2*i]   = l0;
        ((__half2*)lo)[2*i+1] = l1;
    } else {
        __half2 h0, h1;
        h0.x = __float2half(v.x); h0.y = __float2half(v.y);
        h1.x = __float2half(v.z); h1.y = __float2half(v.w);
        ((__half2*)hi)[2*i]   = h0;
        ((__half2*)hi)[2*i+1] = h1;
    }
}

// ---------------- softmax + split (register-resident row, n=2048) ----------------
__global__ __launch_bounds__(256)
void softmax_split_kernel(const float* __restrict__ s, __half* __restrict__ hi,
                          __half* __restrict__ lo)
{
    const long rbase = (long)blockIdx.x * NSEQ;
    const float* row = s + rbase;
    const int tid = threadIdx.x;
    const int warp = tid >> 5, lane = tid & 31;
    __shared__ float red[8];

    float4 x0 = ((const float4*)row)[tid];
    float4 x1 = ((const float4*)row)[tid + 256];

    float m = fmaxf(fmaxf(fmaxf(x0.x, x0.y), fmaxf(x0.z, x0.w)),
                    fmaxf(fmaxf(x1.x, x1.y), fmaxf(x1.z, x1.w)));
    #pragma unroll
    for (int o = 16; o > 0; o >>= 1) m = fmaxf(m, __shfl_xor_sync(0xFFFFFFFF, m, o));
    if (lane == 0) red[warp] = m;
    __syncthreads();
    m = red[lane & 7];
    #pragma unroll
    for (int o = 4; o > 0; o >>= 1) m = fmaxf(m, __shfl_xor_sync(0xFFFFFFFF, m, o));

    x0.x = __expf(x0.x - m); x0.y = __expf(x0.y - m);
    x0.z = __expf(x0.z - m); x0.w = __expf(x0.w - m);
    x1.x = __expf(x1.x - m); x1.y = __expf(x1.y - m);
    x1.z = __expf(x1.z - m); x1.w = __expf(x1.w - m);

    float sum = (x0.x + x0.y) + (x0.z + x0.w) + (x1.x + x1.y) + (x1.z + x1.w);
    #pragma unroll
    for (int o = 16; o > 0; o >>= 1) sum += __shfl_xor_sync(0xFFFFFFFF, sum, o);
    __syncthreads();
    if (lane == 0) red[warp] = sum;
    __syncthreads();
    sum = red[lane & 7];
    #pragma unroll
    for (int o = 4; o > 0; o >>= 1) sum += __shfl_xor_sync(0xFFFFFFFF, sum, o);
    const float inv = 1.f / sum;

    __half2 h[4], l[4];
    split2h(x0.x * inv, h[0].x, l[0].x); split2h(x0.y * inv, h[0].y, l[0].y);
    split2h(x0.z * inv, h[1].x, l[1].x); split2h(x0.w * inv, h[1].y, l[1].y);
    split2h(x1.x * inv, h[2].x, l[2].x); split2h(x1.y * inv, h[2].y, l[2].y);
    split2h(x1.z * inv, h[3].x, l[3].x); split2h(x1.w * inv, h[3].y, l[3].y);

    uint2* hp = (uint2*)(hi + rbase);
    uint2* lp = (uint2*)(lo + rbase);
    uint2 hv0, lv0, hv1, lv1;
    hv0.x = *(uint32_t*)&h[0]; hv0.y = *(uint32_t*)&h[1];
    hv1.x = *(uint32_t*)&h[2]; hv1.y = *(uint32_t*)&h[3];
    lv0.x = *(uint32_t*)&l[0]; lv0.y = *(uint32_t*)&l[1];
    lv1.x = *(uint32_t*)&l[2]; lv1.y = *(uint32_t*)&l[3];
    hp[tid] = hv0; hp[tid + 256] = hv1;
    lp[tid] = lv0; lp[tid + 256] = lv1;
}

// ---------------- launch ----------------
extern "C" void kernel_launch(void* const* d_in, const int* in_sizes, int n_in,
                              void* d_out, int out_size)
{
    (void)in_sizes; (void)n_in; (void)out_size;
    const float* query   = (const float*)d_in[0];
    const float* context = (const float*)d_in[1];
    const float* Wq      = (const float*)d_in[2];
    const float* bq      = (const float*)d_in[3];
    const float* Wv      = (const float*)d_in[4];
    const float* bv      = (const float*)d_in[5];
    const float* Wo      = (const float*)d_in[6];
    const float* bo      = (const float*)d_in[7];
    float* out = (float*)d_out;

    __half *qry_hi,*qry_lo,*ctx_hi,*ctx_lo,*wq,*wv,*wo;
    __half *q_hi,*q_lo,*vT,*attn_hi,*attn_lo,*h_hi,*h_lo;
    float* s;
    cudaGetSymbolAddress((void**)&qry_hi, g_qry_hi);  cudaGetSymbolAddress((void**)&qry_lo, g_qry_lo);
    cudaGetSymbolAddress((void**)&ctx_hi, g_ctx_hi);  cudaGetSymbolAddress((void**)&ctx_lo, g_ctx_lo);
    cudaGetSymbolAddress((void**)&wq, g_wq);
    cudaGetSymbolAddress((void**)&wv, g_wv);
    cudaGetSymbolAddress((void**)&wo, g_wo);
    cudaGetSymbolAddress((void**)&q_hi,   g_q_hi);    cudaGetSymbolAddress((void**)&q_lo,   g_q_lo);
    cudaGetSymbolAddress((void**)&vT,     g_vT);
    cudaGetSymbolAddress((void**)&attn_hi,g_attn_hi); cudaGetSymbolAddress((void**)&attn_lo,g_attn_lo);
    cudaGetSymbolAddress((void**)&h_hi,   g_h_hi);    cudaGetSymbolAddress((void**)&h_lo,   g_h_lo);
    cudaGetSymbolAddress((void**)&s,      g_s);

    cudaFuncSetAttribute(mma_gemm<0>, cudaFuncAttributeMaxDynamicSharedMemorySize, SMEM_G);
    cudaFuncSetAttribute(mma_gemm<1>, cudaFuncAttributeMaxDynamicSharedMemorySize, SMEM_G);
    cudaFuncSetAttribute(qv_gemm,     cudaFuncAttributeMaxDynamicSharedMemorySize, SMEM_G);

    const float scale = 1.0f / sqrtf((float)DDIM);

    // 0) split/round all fp32 inputs -> fp16 (one launch)
    {
        int total = 2 * NQ4 + 3 * NW4;
        split_all_kernel<<<(total + 255) / 256, 256>>>(
            query, context, Wq, Wv, Wo,
            qry_hi, qry_lo, ctx_hi, ctx_lo, wq, wv, wo);
    }

    // 1+2) q = query@Wq^T + bq (split out)  AND  v^T = (context@Wv^T + bv)^T (rounded out)
    qv_gemm<<<dim3(DDIM/128, MFLAT/128, 2), 256, SMEM_G>>>(
        qry_hi, qry_lo, wq, bq, q_hi, q_lo,
        ctx_hi, ctx_lo, wv, bv, vT);

    // 3) scores = scale * q @ context^T  (batched; B = ctx rounded = ctx_hi) -> fp32 s
    mma_gemm<0><<<dim3(NSEQ/128, NSEQ/128, BB), 256, SMEM_G>>>(
        q_hi, q_lo, ctx_hi, nullptr, s, nullptr, nullptr,
        NSEQ, NSEQ, DDIM, scale,
        (long)NSEQ * DDIM, (long)NSEQ * DDIM, (long)NSEQ * NSEQ);

    // 4) softmax rows -> split attn
    softmax_split_kernel<<<BB * NSEQ, 256>>>(s, attn_hi, attn_lo);

    // 5) h = attn @ v = attn(split) @ (v^T rounded)^T  (batched) -> split h
    mma_gemm<1><<<dim3(DDIM/128, NSEQ/128, BB), 256, SMEM_G>>>(
        attn_hi, attn_lo, vT, nullptr, nullptr, h_hi, h_lo,
        NSEQ, DDIM, NSEQ, 1.0f,
        (long)NSEQ * NSEQ, (long)DDIM * NSEQ, (long)NSEQ * DDIM);

    // 6) out = h(split) @ Wo^T(rounded) + bo -> fp32
    mma_gemm<0><<<dim3(DDIM/128, MFLAT/128, 1), 256, SMEM_G>>>(
        h_hi, h_lo, wo, bo, out, nullptr, nullptr,
        MFLAT, DDIM, DDIM, 1.0f, 0, 0, 0);
}

// round 11
// speedup vs baseline: 4.0952x; 1.4445x over previous
#include <cuda_runtime.h>
#include <cuda_fp16.h>
#include <cstdint>
#include <math.h>

#define BB 8
#define NSEQ 2048
#define DDIM 512
#define MFLAT (BB*NSEQ)

// ---------------- scratch (device globals: allocation-free) ----------------
__device__ __half g_qry_hi[MFLAT*DDIM], g_qry_lo[MFLAT*DDIM];
__device__ __half g_ctx_hi[MFLAT*DDIM], g_ctx_lo[MFLAT*DDIM];
__device__ __half g_wq[DDIM*DDIM], g_wv[DDIM*DDIM], g_wo[DDIM*DDIM];   // rounded B operands
__device__ __half g_q[MFLAT*DDIM];                                     // rounded q
__device__ __half g_vT[MFLAT*DDIM];                                    // rounded, transposed per batch
__device__ float  g_s[(size_t)BB*NSEQ*NSEQ];
__device__ __half g_attn[(size_t)BB*NSEQ*NSEQ];                        // rounded attn
__device__ __half g_h_hi[MFLAT*DDIM],  g_h_lo[MFLAT*DDIM];

// ---------------- helpers ----------------
__device__ __forceinline__ uint32_t smem_u32(const void* p){
    uint32_t a;
    asm("{ .reg .u64 t; cvta.to.shared.u64 t, %1; cvt.u32.u64 %0, t; }" : "=r"(a) : "l"(p));
    return a;
}
__device__ __forceinline__ void split2h(float v, __half& h, __half& l){
    h = __float2half(v);
    l = __float2half(v - __half2float(h));
}

#define CP_ASYNC16(sm, gm) \
    asm volatile("cp.async.cg.shared.global [%0], [%1], 16;" :: "r"(sm), "l"(gm))
#define CP_COMMIT() asm volatile("cp.async.commit_group;" ::: "memory")
#define CP_WAIT2()  asm volatile("cp.async.wait_group 2;" ::: "memory")
#define CP_WAIT1()  asm volatile("cp.async.wait_group 1;" ::: "memory")
#define CP_WAIT0()  asm volatile("cp.async.wait_group 0;" ::: "memory")

__device__ __forceinline__ void ldmatrix_x4(uint32_t& r0, uint32_t& r1, uint32_t& r2, uint32_t& r3, uint32_t addr){
    asm volatile("ldmatrix.sync.aligned.m8n8.x4.shared.b16 {%0,%1,%2,%3}, [%4];"
        : "=r"(r0), "=r"(r1), "=r"(r2), "=r"(r3) : "r"(addr));
}
__device__ __forceinline__ void mma_f16(float* c, const uint32_t* a, const uint32_t* b){
    asm volatile(
        "mma.sync.aligned.m16n8k16.row.col.f32.f16.f16.f32 "
        "{%0,%1,%2,%3}, {%4,%5,%6,%7}, {%8,%9}, {%0,%1,%2,%3};"
        : "+f"(c[0]), "+f"(c[1]), "+f"(c[2]), "+f"(c[3])
        : "r"(a[0]), "r"(a[1]), "r"(a[2]), "r"(a[3]), "r"(b[0]), "r"(b[1]));
}

// ---------------- GEMM config (CTA 128x128, warp 64x32, BK=32, 4 stages) ----------------
#define PITCH 80
#define TILEB (128*PITCH)
#define STAGEB (2*TILEB)
#define NSTAGE 4
#define SMEM_G (NSTAGE*STAGEB)     // 81920 B -> 2 CTAs/SM

// Mainloop: acc += sum_{seg<NSEGS} Aseg[seg] @ B^T. One __syncthreads per iter.
#define GEMM_MAINLOOP(Aseg, Bop, Kdim, NSEGS)                                        \
    const int tps = (Kdim) >> 5;                                                     \
    const int T = (NSEGS) * tps;                                                     \
    const int ldRow = tid >> 1;                                                      \
    const int ldOff = (tid & 1) * 32;                                                \
    auto issue = [&](int t){                                                         \
        const int st = t & 3;                                                        \
        const int seg = t / tps;                                                     \
        const int kk  = (t - seg * tps) << 5;                                        \
        const __half* Ap = Aseg[seg] + (long)(rowBase + ldRow) * (Kdim) + kk + (ldOff >> 1); \
        const __half* Bp = (Bop) + (long)(colBase + ldRow) * (Kdim) + kk + (ldOff >> 1);     \
        const uint32_t sa = smBase + st * STAGEB + ldRow * PITCH + ldOff;            \
        const uint32_t sb = sa + TILEB;                                              \
        CP_ASYNC16(sa,      Ap);                                                     \
        CP_ASYNC16(sa + 16, Ap + 8);                                                 \
        CP_ASYNC16(sb,      Bp);                                                     \
        CP_ASYNC16(sb + 16, Bp + 8);                                                 \
        CP_COMMIT();                                                                 \
    };                                                                               \
    issue(0); issue(1); issue(2);                                                    \
    const uint32_t aLaneOff = (uint32_t)(warpM*64 + (lane & 15)) * PITCH + ((lane >> 4) & 1) * 16; \
    const uint32_t bLaneOff = (uint32_t)(warpN*32 + (lane & 7) + ((lane >> 4) & 1) * 8) * PITCH    \
                            + ((lane >> 3) & 1) * 16;                                \
    for (int t = 0; t < T; t++) {                                                    \
        const int rem = T - 1 - t;                                                   \
        if (rem >= 2) { CP_WAIT2(); } else if (rem == 1) { CP_WAIT1(); } else { CP_WAIT0(); } \
        __syncthreads();                                                             \
        if (t + 3 < T) issue(t + 3);                                                 \
        const int st = t & 3;                                                        \
        const uint32_t aBase = smBase + st * STAGEB + aLaneOff;                      \
        const uint32_t bBase = smBase + st * STAGEB + TILEB + bLaneOff;              \
        _Pragma("unroll")                                                            \
        for (int ks = 0; ks < 2; ks++) {                                             \
            const uint32_t kByte = ks * 32;                                          \
            uint32_t afr[4][4];                                                      \
            _Pragma("unroll")                                                        \
            for (int mt = 0; mt < 4; mt++)                                           \
                ldmatrix_x4(afr[mt][0], afr[mt][1], afr[mt][2], afr[mt][3],          \
                            aBase + mt * 16 * PITCH + kByte);                        \
            uint32_t bfr[2][4];                                                      \
            _Pragma("unroll")                                                        \
            for (int p = 0; p < 2; p++)                                              \
                ldmatrix_x4(bfr[p][0], bfr[p][1], bfr[p][2], bfr[p][3],              \
                            bBase + p * 16 * PITCH + kByte);                         \
            _Pragma("unroll")                                                        \
            for (int mt = 0; mt < 4; mt++)                                           \
                _Pragma("unroll")                                                    \
                for (int nt = 0; nt < 4; nt++)                                       \
                    mma_f16(acc[mt][nt], afr[mt], &bfr[nt >> 1][(nt & 1) * 2]);      \
        }                                                                            \
    }

// ---------------- generic GEMM ----------------
// MODE 0: fp32 out (+bias, alpha). MODE 1: split fp16 out (hi/lo).
// NSEG: number of A segments (1 = A single, 2 = A hi/lo).
template<int MODE, int NSEG>
__global__ __launch_bounds__(256, 2)
void mma_gemm(const __half* __restrict__ Ahi, const __half* __restrict__ Alo,
              const __half* __restrict__ B,
              const float* __restrict__ bias,
              float* __restrict__ outF, __half* __restrict__ outHi, __half* __restrict__ outLo,
              int M, int N, int K, float alpha,
              long sA, long sB, long sC)
{
    extern __shared__ __align__(128) char smem[];
    const int tid  = threadIdx.x;
    const int warp = tid >> 5;
    const int lane = tid & 31;
    const int warpM = warp >> 2;
    const int warpN = warp & 3;

    const int z = blockIdx.z;
    Ahi += (long)z * sA;
    if (NSEG == 2) Alo += (long)z * sA;
    B   += (long)z * sB;
    if (MODE == 0) { outF += (long)z * sC; }
    else { outHi += (long)z * sC; outLo += (long)z * sC; }

    const int rowBase = blockIdx.y * 128;
    const int colBase = blockIdx.x * 128;
    const uint32_t smBase = smem_u32(smem);

    const __half* Aseg[2] = {Ahi, (NSEG == 2) ? Alo : Ahi};

    float acc[4][4][4];
    #pragma unroll
    for (int i = 0; i < 4; i++)
        #pragma unroll
        for (int j = 0; j < 4; j++)
            #pragma unroll
            for (int c = 0; c < 4; c++) acc[i][j][c] = 0.f;

    GEMM_MAINLOOP(Aseg, B, K, NSEG)

    #pragma unroll
    for (int mt = 0; mt < 4; mt++) {
        const int r0 = rowBase + warpM*64 + mt*16 + (lane >> 2);
        #pragma unroll
        for (int nt = 0; nt < 4; nt++) {
            const int gc = colBase + warpN*32 + nt*8 + (lane & 3)*2;
            float v00 = acc[mt][nt][0] * alpha;
            float v01 = acc[mt][nt][1] * alpha;
            float v10 = acc[mt][nt][2] * alpha;
            float v11 = acc[mt][nt][3] * alpha;
            if (bias) {
                const float b0 = bias[gc], b1 = bias[gc+1];
                v00 += b0; v01 += b1; v10 += b0; v11 += b1;
            }
            if (MODE == 0) {
                *(float2*)&outF[(long)r0 * N + gc]       = make_float2(v00, v01);
                *(float2*)&outF[(long)(r0+8) * N + gc]   = make_float2(v10, v11);
            } else {
                __half2 h, l;
                split2h(v00, h.x, l.x); split2h(v01, h.y, l.y);
                *(__half2*)&outHi[(long)r0 * N + gc] = h;
                *(__half2*)&outLo[(long)r0 * N + gc] = l;
                split2h(v10, h.x, l.x); split2h(v11, h.y, l.y);
                *(__half2*)&outHi[(long)(r0+8) * N + gc] = h;
                *(__half2*)&outLo[(long)(r0+8) * N + gc] = l;
            }
        }
    }
}

// ---------------- combined Q/V projection (z=0: q rounded out, z=1: v^T rounded out) ----------
__global__ __launch_bounds__(256, 2)
void qv_gemm(const __half* __restrict__ qryh, const __half* __restrict__ qryl,
             const __half* __restrict__ wq, const float* __restrict__ bq,
             __half* __restrict__ q,
             const __half* __restrict__ ctxh, const __half* __restrict__ ctxl,
             const __half* __restrict__ wv, const float* __restrict__ bv,
             __half* __restrict__ vt)
{
    extern __shared__ __align__(128) char smem[];
    const int tid  = threadIdx.x;
    const int warp = tid >> 5;
    const int lane = tid & 31;
    const int warpM = warp >> 2;
    const int warpN = warp & 3;
    const int isV = blockIdx.z;

    const int rowBase = blockIdx.y * 128;
    const int colBase = blockIdx.x * 128;
    const uint32_t smBase = smem_u32(smem);

    const __half* Aseg[2];
    Aseg[0] = isV ? ctxh : qryh;
    Aseg[1] = isV ? ctxl : qryl;
    const __half* B   = isV ? wv : wq;
    const float* bias = isV ? bv : bq;

    float acc[4][4][4];
    #pragma unroll
    for (int i = 0; i < 4; i++)
        #pragma unroll
        for (int j = 0; j < 4; j++)
            #pragma unroll
            for (int c = 0; c < 4; c++) acc[i][j][c] = 0.f;

    GEMM_MAINLOOP(Aseg, B, DDIM, 2)

    #pragma unroll
    for (int mt = 0; mt < 4; mt++) {
        const int r0 = rowBase + warpM*64 + mt*16 + (lane >> 2);
        #pragma unroll
        for (int nt = 0; nt < 4; nt++) {
            const int gc = colBase + warpN*32 + nt*8 + (lane & 3)*2;
            const float b0 = bias[gc], b1 = bias[gc+1];
            float v00 = acc[mt][nt][0] + b0;
            float v01 = acc[mt][nt][1] + b1;
            float v10 = acc[mt][nt][2] + b0;
            float v11 = acc[mt][nt][3] + b1;
            if (!isV) {        // q rounded single fp16
                __half2 h;
                h.x = __float2half(v00); h.y = __float2half(v01);
                *(__half2*)&q[(long)r0 * DDIM + gc] = h;
                h.x = __float2half(v10); h.y = __float2half(v11);
                *(__half2*)&q[(long)(r0+8) * DDIM + gc] = h;
            } else {           // v^T per batch [DDIM, NSEQ], rounded single fp16
                const int rows[2] = {r0, r0 + 8};
                const float vals[2][2] = {{v00, v01}, {v10, v11}};
                #pragma unroll
                for (int rr = 0; rr < 2; rr++) {
                    const int bb = rows[rr] >> 11, tok = rows[rr] & 2047;
                    const long base = (long)bb * (DDIM * NSEQ) + tok;
                    #pragma unroll
                    for (int cc = 0; cc < 2; cc++)
                        vt[base + (long)(gc + cc) * NSEQ] = __float2half(vals[rr][cc]);
                }
            }
        }
    }
}

// ---------------- fused input split/round ----------------
#define NQ4 ((MFLAT*DDIM)/4)
#define NW4 ((DDIM*DDIM)/4)
__global__ __launch_bounds__(256)
void split_all_kernel(const float* __restrict__ query, const float* __restrict__ context,
                      const float* __restrict__ Wq, const float* __restrict__ Wv, const float* __restrict__ Wo,
                      __half* __restrict__ qryh, __half* __restrict__ qryl,
                      __half* __restrict__ ctxh, __half* __restrict__ ctxl,
                      __half* __restrict__ wq, __half* __restrict__ wv, __half* __restrict__ wo)
{
    int i = blockIdx.x * blockDim.x + threadIdx.x;
    const float* src; __half *hi, *lo = nullptr;
    if (i < NQ4)                  { src = query;   hi = qryh; lo = qryl; }
    else if ((i -= NQ4) < NQ4)    { src = context; hi = ctxh; lo = ctxl; }
    else if ((i -= NQ4) < NW4)    { src = Wq;      hi = wq; }
    else if ((i -= NW4) < NW4)    { src = Wv;      hi = wv; }
    else if ((i -= NW4) < NW4)    { src = Wo;      hi = wo; }
    else return;
    float4 v = ((const float4*)src)[i];
    if (lo) {
        __half2 h0, h1, l0, l1;
        split2h(v.x, h0.x, l0.x); split2h(v.y, h0.y, l0.y);
        split2h(v.z, h1.x, l1.x); split2h(v.w, h1.y, l1.y);
        ((__half2*)hi)[2*i]   = h0;
        ((__half2*)hi)[2*i+1] = h1;
        ((__half2*)lo)[2*i]   = l0;
        ((__half2*)lo)[2*i+1] = l1;
    } else {
        __half2 h0, h1;
        h0.x = __float2half(v.x); h0.y = __float2half(v.y);
        h1.x = __float2half(v.z); h1.y = __float2half(v.w);
        ((__half2*)hi)[2*i]   = h0;
        ((__half2*)hi)[2*i+1] = h1;
    }
}

// ---------------- softmax + round to single fp16 (register-resident row, n=2048) ----------------
__global__ __launch_bounds__(256)
void softmax_round_kernel(const float* __restrict__ s, __half* __restrict__ attn)
{
    const long rbase = (long)blockIdx.x * NSEQ;
    const float* row = s + rbase;
    const int tid = threadIdx.x;
    const int warp = tid >> 5, lane = tid & 31;
    __shared__ float red[8];

    float4 x0 = ((const float4*)row)[tid];
    float4 x1 = ((const float4*)row)[tid + 256];

    float m = fmaxf(fmaxf(fmaxf(x0.x, x0.y), fmaxf(x0.z, x0.w)),
                    fmaxf(fmaxf(x1.x, x1.y), fmaxf(x1.z, x1.w)));
    #pragma unroll
    for (int o = 16; o > 0; o >>= 1) m = fmaxf(m, __shfl_xor_sync(0xFFFFFFFF, m, o));
    if (lane == 0) red[warp] = m;
    __syncthreads();
    m = red[lane & 7];
    #pragma unroll
    for (int o = 4; o > 0; o >>= 1) m = fmaxf(m, __shfl_xor_sync(0xFFFFFFFF, m, o));

    x0.x = __expf(x0.x - m); x0.y = __expf(x0.y - m);
    x0.z = __expf(x0.z - m); x0.w = __expf(x0.w - m);
    x1.x = __expf(x1.x - m); x1.y = __expf(x1.y - m);
    x1.z = __expf(x1.z - m); x1.w = __expf(x1.w - m);

    float sum = (x0.x + x0.y) + (x0.z + x0.w) + (x1.x + x1.y) + (x1.z + x1.w);
    #pragma unroll
    for (int o = 16; o > 0; o >>= 1) sum += __shfl_xor_sync(0xFFFFFFFF, sum, o);
    __syncthreads();
    if (lane == 0) red[warp] = sum;
    __syncthreads();
    sum = red[lane & 7];
    #pragma unroll
    for (int o = 4; o > 0; o >>= 1) sum += __shfl_xor_sync(0xFFFFFFFF, sum, o);
    const float inv = 1.f / sum;

    __half2 h[4];
    h[0].x = __float2half(x0.x * inv); h[0].y = __float2half(x0.y * inv);
    h[1].x = __float2half(x0.z * inv); h[1].y = __float2half(x0.w * inv);
    h[2].x = __float2half(x1.x * inv); h[2].y = __float2half(x1.y * inv);
    h[3].x = __float2half(x1.z * inv); h[3].y = __float2half(x1.w * inv);

    uint2* hp = (uint2*)(attn + rbase);
    uint2 hv0, hv1;
    hv0.x = *(uint32_t*)&h[0]; hv0.y = *(uint32_t*)&h[1];
    hv1.x = *(uint32_t*)&h[2]; hv1.y = *(uint32_t*)&h[3];
    hp[tid] = hv0; hp[tid + 256] = hv1;
}

// ---------------- launch ----------------
extern "C" void kernel_launch(void* const* d_in, const int* in_sizes, int n_in,
                              void* d_out, int out_size)
{
    (void)in_sizes; (void)n_in; (void)out_size;
    const float* query   = (const float*)d_in[0];
    const float* context = (const float*)d_in[1];
    const float* Wq      = (const float*)d_in[2];
    const float* bq      = (const float*)d_in[3];
    const float* Wv      = (const float*)d_in[4];
    const float* bv      = (const float*)d_in[5];
    const float* Wo      = (const float*)d_in[6];
    const float* bo      = (const float*)d_in[7];
    float* out = (float*)d_out;

    __half *qry_hi,*qry_lo,*ctx_hi,*ctx_lo,*wq,*wv,*wo;
    __half *q,*vT,*attn,*h_hi,*h_lo;
    float* s;
    cudaGetSymbolAddress((void**)&qry_hi, g_qry_hi);  cudaGetSymbolAddress((void**)&qry_lo, g_qry_lo);
    cudaGetSymbolAddress((void**)&ctx_hi, g_ctx_hi);  cudaGetSymbolAddress((void**)&ctx_lo, g_ctx_lo);
    cudaGetSymbolAddress((void**)&wq, g_wq);
    cudaGetSymbolAddress((void**)&wv, g_wv);
    cudaGetSymbolAddress((void**)&wo, g_wo);
    cudaGetSymbolAddress((void**)&q,  g_q);
    cudaGetSymbolAddress((void**)&vT, g_vT);
    cudaGetSymbolAddress((void**)&attn, g_attn);
    cudaGetSymbolAddress((void**)&h_hi, g_h_hi);      cudaGetSymbolAddress((void**)&h_lo, g_h_lo);
    cudaGetSymbolAddress((void**)&s, g_s);

    cudaFuncSetAttribute((const void*)mma_gemm<0,1>, cudaFuncAttributeMaxDynamicSharedMemorySize, SMEM_G);
    cudaFuncSetAttribute((const void*)mma_gemm<1,1>, cudaFuncAttributeMaxDynamicSharedMemorySize, SMEM_G);
    cudaFuncSetAttribute((const void*)mma_gemm<0,2>, cudaFuncAttributeMaxDynamicSharedMemorySize, SMEM_G);
    cudaFuncSetAttribute((const void*)qv_gemm,       cudaFuncAttributeMaxDynamicSharedMemorySize, SMEM_G);

    const float scale = 1.0f / sqrtf((float)DDIM);

    // 0) split/round all fp32 inputs -> fp16 (one launch)
    {
        int total = 2 * NQ4 + 3 * NW4;
        split_all_kernel<<<(total + 255) / 256, 256>>>(
            query, context, Wq, Wv, Wo,
            qry_hi, qry_lo, ctx_hi, ctx_lo, wq, wv, wo);
    }

    // 1+2) q = round(query@Wq^T + bq)  AND  v^T = round((context@Wv^T + bv)^T)
    qv_gemm<<<dim3(DDIM/128, MFLAT/128, 2), 256, SMEM_G>>>(
        qry_hi, qry_lo, wq, bq, q,
        ctx_hi, ctx_lo, wv, bv, vT);

    // 3) scores = scale * q @ ctx^T  (batched, 1-product) -> fp32 s
    mma_gemm<0,1><<<dim3(NSEQ/128, NSEQ/128, BB), 256, SMEM_G>>>(
        q, nullptr, ctx_hi, nullptr, s, nullptr, nullptr,
        NSEQ, NSEQ, DDIM, scale,
        (long)NSEQ * DDIM, (long)NSEQ * DDIM, (long)NSEQ * NSEQ);

    // 4) softmax rows -> rounded attn
    softmax_round_kernel<<<BB * NSEQ, 256>>>(s, attn);

    // 5) h = attn @ (v^T)^T  (batched, 1-product) -> split h
    mma_gemm<1,1><<<dim3(DDIM/128, NSEQ/128, BB), 256, SMEM_G>>>(
        attn, nullptr, vT, nullptr, nullptr, h_hi, h_lo,
        NSEQ, DDIM, NSEQ, 1.0f,
        (long)NSEQ * NSEQ, (long)DDIM * NSEQ, (long)NSEQ * DDIM);

    // 6) out = h(split) @ Wo^T + bo  (2-product) -> fp32
    mma_gemm<0,2><<<dim3(DDIM/128, MFLAT/128, 1), 256, SMEM_G>>>(
        h_hi, h_lo, wo, bo, out, nullptr, nullptr,
        MFLAT, DDIM, DDIM, 1.0f, 0, 0, 0);
}

// round 12
// speedup vs baseline: 5.1771x; 1.2642x over previous
#include <cuda_runtime.h>
#include <cuda_fp16.h>
#include <cstdint>
#include <math.h>

#define BB 8
#define NSEQ 2048
#define DDIM 512
#define MFLAT (BB*NSEQ)

// ---------------- scratch (device globals: allocation-free) ----------------
__device__ __half g_qry[MFLAT*DDIM], g_ctx[MFLAT*DDIM];
__device__ __half g_wq[DDIM*DDIM], g_wv[DDIM*DDIM], g_wo[DDIM*DDIM];
__device__ __half g_q[MFLAT*DDIM];
__device__ __half g_vT[MFLAT*DDIM];          // transposed per batch [DDIM, NSEQ]
__device__ float  g_s[(size_t)BB*NSEQ*NSEQ];
__device__ __half g_attn[(size_t)BB*NSEQ*NSEQ];
__device__ __half g_h[MFLAT*DDIM];

// ---------------- helpers ----------------
__device__ __forceinline__ uint32_t smem_u32(const void* p){
    uint32_t a;
    asm("{ .reg .u64 t; cvta.to.shared.u64 t, %1; cvt.u32.u64 %0, t; }" : "=r"(a) : "l"(p));
    return a;
}

#define CP_ASYNC16(sm, gm) \
    asm volatile("cp.async.cg.shared.global [%0], [%1], 16;" :: "r"(sm), "l"(gm))
#define CP_COMMIT() asm volatile("cp.async.commit_group;" ::: "memory")
#define CP_WAIT2()  asm volatile("cp.async.wait_group 2;" ::: "memory")
#define CP_WAIT1()  asm volatile("cp.async.wait_group 1;" ::: "memory")
#define CP_WAIT0()  asm volatile("cp.async.wait_group 0;" ::: "memory")

__device__ __forceinline__ void ldmatrix_x4(uint32_t& r0, uint32_t& r1, uint32_t& r2, uint32_t& r3, uint32_t addr){
    asm volatile("ldmatrix.sync.aligned.m8n8.x4.shared.b16 {%0,%1,%2,%3}, [%4];"
        : "=r"(r0), "=r"(r1), "=r"(r2), "=r"(r3) : "r"(addr));
}
__device__ __forceinline__ void mma_f16(float* c, const uint32_t* a, const uint32_t* b){
    asm volatile(
        "mma.sync.aligned.m16n8k16.row.col.f32.f16.f16.f32 "
        "{%0,%1,%2,%3}, {%4,%5,%6,%7}, {%8,%9}, {%0,%1,%2,%3};"
        : "+f"(c[0]), "+f"(c[1]), "+f"(c[2]), "+f"(c[3])
        : "r"(a[0]), "r"(a[1]), "r"(a[2]), "r"(a[3]), "r"(b[0]), "r"(b[1]));
}

// ---------------- GEMM config (CTA 128x128, warp 64x32, BK=32, 4 stages) ----------------
#define PITCH 80
#define TILEB (128*PITCH)
#define STAGEB (2*TILEB)
#define NSTAGE 4
#define SMEM_G (NSTAGE*STAGEB)     // 81920 B -> 2 CTAs/SM

// Mainloop: acc += A @ B^T (single product). One __syncthreads per iter.
#define GEMM_MAINLOOP(Aop, Bop, Kdim)                                                \
    const int T = (Kdim) >> 5;                                                       \
    const int ldRow = tid >> 1;                                                      \
    const int ldOff = (tid & 1) * 32;                                                \
    auto issue = [&](int t){                                                         \
        const int st = t & 3;                                                        \
        const int kk = t << 5;                                                       \
        const __half* Ap = (Aop) + (long)(rowBase + ldRow) * (Kdim) + kk + (ldOff >> 1); \
        const __half* Bp = (Bop) + (long)(colBase + ldRow) * (Kdim) + kk + (ldOff >> 1); \
        const uint32_t sa = smBase + st * STAGEB + ldRow * PITCH + ldOff;            \
        const uint32_t sb = sa + TILEB;                                              \
        CP_ASYNC16(sa,      Ap);                                                     \
        CP_ASYNC16(sa + 16, Ap + 8);                                                 \
        CP_ASYNC16(sb,      Bp);                                                     \
        CP_ASYNC16(sb + 16, Bp + 8);                                                 \
        CP_COMMIT();                                                                 \
    };                                                                               \
    issue(0); issue(1); issue(2);                                                    \
    const uint32_t aLaneOff = (uint32_t)(warpM*64 + (lane & 15)) * PITCH + ((lane >> 4) & 1) * 16; \
    const uint32_t bLaneOff = (uint32_t)(warpN*32 + (lane & 7) + ((lane >> 4) & 1) * 8) * PITCH    \
                            + ((lane >> 3) & 1) * 16;                                \
    for (int t = 0; t < T; t++) {                                                    \
        const int rem = T - 1 - t;                                                   \
        if (rem >= 2) { CP_WAIT2(); } else if (rem == 1) { CP_WAIT1(); } else { CP_WAIT0(); } \
        __syncthreads();                                                             \
        if (t + 3 < T) issue(t + 3);                                                 \
        const int st = t & 3;                                                        \
        const uint32_t aBase = smBase + st * STAGEB + aLaneOff;                      \
        const uint32_t bBase = smBase + st * STAGEB + TILEB + bLaneOff;              \
        _Pragma("unroll")                                                            \
        for (int ks = 0; ks < 2; ks++) {                                             \
            const uint32_t kByte = ks * 32;                                          \
            uint32_t afr[4][4];                                                      \
            _Pragma("unroll")                                                        \
            for (int mt = 0; mt < 4; mt++)                                           \
                ldmatrix_x4(afr[mt][0], afr[mt][1], afr[mt][2], afr[mt][3],          \
                            aBase + mt * 16 * PITCH + kByte);                        \
            uint32_t bfr[2][4];                                                      \
            _Pragma("unroll")                                                        \
            for (int p = 0; p < 2; p++)                                              \
                ldmatrix_x4(bfr[p][0], bfr[p][1], bfr[p][2], bfr[p][3],              \
                            bBase + p * 16 * PITCH + kByte);                         \
            _Pragma("unroll")                                                        \
            for (int mt = 0; mt < 4; mt++)                                           \
                _Pragma("unroll")                                                    \
                for (int nt = 0; nt < 4; nt++)                                       \
                    mma_f16(acc[mt][nt], afr[mt], &bfr[nt >> 1][(nt & 1) * 2]);      \
        }                                                                            \
    }

// ---------------- generic GEMM ----------------
// MODE 0: fp32 out (+bias, alpha). MODE 1: rounded fp16 out.
template<int MODE>
__global__ __launch_bounds__(256, 2)
void mma_gemm(const __half* __restrict__ A, const __half* __restrict__ B,
              const float* __restrict__ bias,
              float* __restrict__ outF, __half* __restrict__ outH,
              int M, int N, int K, float alpha,
              long sA, long sB, long sC)
{
    extern __shared__ __align__(128) char smem[];
    const int tid  = threadIdx.x;
    const int warp = tid >> 5;
    const int lane = tid & 31;
    const int warpM = warp >> 2;
    const int warpN = warp & 3;

    const int z = blockIdx.z;
    A += (long)z * sA;
    B += (long)z * sB;
    if (MODE == 0) { outF += (long)z * sC; } else { outH += (long)z * sC; }

    const int rowBase = blockIdx.y * 128;
    const int colBase = blockIdx.x * 128;
    const uint32_t smBase = smem_u32(smem);

    float acc[4][4][4];
    #pragma unroll
    for (int i = 0; i < 4; i++)
        #pragma unroll
        for (int j = 0; j < 4; j++)
            #pragma unroll
            for (int c = 0; c < 4; c++) acc[i][j][c] = 0.f;

    GEMM_MAINLOOP(A, B, K)

    #pragma unroll
    for (int mt = 0; mt < 4; mt++) {
        const int r0 = rowBase + warpM*64 + mt*16 + (lane >> 2);
        #pragma unroll
        for (int nt = 0; nt < 4; nt++) {
            const int gc = colBase + warpN*32 + nt*8 + (lane & 3)*2;
            float v00 = acc[mt][nt][0] * alpha;
            float v01 = acc[mt][nt][1] * alpha;
            float v10 = acc[mt][nt][2] * alpha;
            float v11 = acc[mt][nt][3] * alpha;
            if (bias) {
                const float b0 = bias[gc], b1 = bias[gc+1];
                v00 += b0; v01 += b1; v10 += b0; v11 += b1;
            }
            if (MODE == 0) {
                *(float2*)&outF[(long)r0 * N + gc]       = make_float2(v00, v01);
                *(float2*)&outF[(long)(r0+8) * N + gc]   = make_float2(v10, v11);
            } else {
                __half2 h;
                h.x = __float2half(v00); h.y = __float2half(v01);
                *(__half2*)&outH[(long)r0 * N + gc] = h;
                h.x = __float2half(v10); h.y = __float2half(v11);
                *(__half2*)&outH[(long)(r0+8) * N + gc] = h;
            }
        }
    }
}

// ---------------- combined Q/V projection (z=0: q rounded out, z=1: v^T rounded out) ----------
__global__ __launch_bounds__(256, 2)
void qv_gemm(const __half* __restrict__ qry, const __half* __restrict__ wq,
             const float* __restrict__ bq, __half* __restrict__ q,
             const __half* __restrict__ ctx, const __half* __restrict__ wv,
             const float* __restrict__ bv, __half* __restrict__ vt)
{
    extern __shared__ __align__(128) char smem[];
    const int tid  = threadIdx.x;
    const int warp = tid >> 5;
    const int lane = tid & 31;
    const int warpM = warp >> 2;
    const int warpN = warp & 3;
    const int isV = blockIdx.z;

    const int rowBase = blockIdx.y * 128;
    const int colBase = blockIdx.x * 128;
    const uint32_t smBase = smem_u32(smem);

    const __half* A   = isV ? ctx : qry;
    const __half* B   = isV ? wv  : wq;
    const float* bias = isV ? bv  : bq;

    float acc[4][4][4];
    #pragma unroll
    for (int i = 0; i < 4; i++)
        #pragma unroll
        for (int j = 0; j < 4; j++)
            #pragma unroll
            for (int c = 0; c < 4; c++) acc[i][j][c] = 0.f;

    GEMM_MAINLOOP(A, B, DDIM)

    #pragma unroll
    for (int mt = 0; mt < 4; mt++) {
        const int r0 = rowBase + warpM*64 + mt*16 + (lane >> 2);
        #pragma unroll
        for (int nt = 0; nt < 4; nt++) {
            const int gc = colBase + warpN*32 + nt*8 + (lane & 3)*2;
            const float b0 = bias[gc], b1 = bias[gc+1];
            float v00 = acc[mt][nt][0] + b0;
            float v01 = acc[mt][nt][1] + b1;
            float v10 = acc[mt][nt][2] + b0;
            float v11 = acc[mt][nt][3] + b1;
            if (!isV) {        // q rounded fp16, row-major
                __half2 h;
                h.x = __float2half(v00); h.y = __float2half(v01);
                *(__half2*)&q[(long)r0 * DDIM + gc] = h;
                h.x = __float2half(v10); h.y = __float2half(v11);
                *(__half2*)&q[(long)(r0+8) * DDIM + gc] = h;
            } else {           // v^T per batch [DDIM, NSEQ], rounded fp16
                const int rows[2] = {r0, r0 + 8};
                const float vals[2][2] = {{v00, v01}, {v10, v11}};
                #pragma unroll
                for (int rr = 0; rr < 2; rr++) {
                    const int bb = rows[rr] >> 11, tok = rows[rr] & 2047;
                    const long base = (long)bb * (DDIM * NSEQ) + tok;
                    #pragma unroll
                    for (int cc = 0; cc < 2; cc++)
                        vt[base + (long)(gc + cc) * NSEQ] = __float2half(vals[rr][cc]);
                }
            }
        }
    }
}

// ---------------- fused input round (fp32 -> fp16) ----------------
#define NQ4 ((MFLAT*DDIM)/4)
#define NW4 ((DDIM*DDIM)/4)
__global__ __launch_bounds__(256)
void round_all_kernel(const float* __restrict__ query, const float* __restrict__ context,
                      const float* __restrict__ Wq, const float* __restrict__ Wv, const float* __restrict__ Wo,
                      __half* __restrict__ qry, __half* __restrict__ ctx,
                      __half* __restrict__ wq, __half* __restrict__ wv, __half* __restrict__ wo)
{
    int i = blockIdx.x * blockDim.x + threadIdx.x;
    const float* src; __half* dst;
    if (i < NQ4)                  { src = query;   dst = qry; }
    else if ((i -= NQ4) < NQ4)    { src = context; dst = ctx; }
    else if ((i -= NQ4) < NW4)    { src = Wq;      dst = wq; }
    else if ((i -= NW4) < NW4)    { src = Wv;      dst = wv; }
    else if ((i -= NW4) < NW4)    { src = Wo;      dst = wo; }
    else return;
    float4 v = ((const float4*)src)[i];
    __half2 h0, h1;
    h0.x = __float2half(v.x); h0.y = __float2half(v.y);
    h1.x = __float2half(v.z); h1.y = __float2half(v.w);
    ((__half2*)dst)[2*i]   = h0;
    ((__half2*)dst)[2*i+1] = h1;
}

// ---------------- softmax + round to fp16 (register-resident row, n=2048) ----------------
__global__ __launch_bounds__(256)
void softmax_round_kernel(const float* __restrict__ s, __half* __restrict__ attn)
{
    const long rbase = (long)blockIdx.x * NSEQ;
    const float* row = s + rbase;
    const int tid = threadIdx.x;
    const int warp = tid >> 5, lane = tid & 31;
    __shared__ float red[8];

    float4 x0 = ((const float4*)row)[tid];
    float4 x1 = ((const float4*)row)[tid + 256];

    float m = fmaxf(fmaxf(fmaxf(x0.x, x0.y), fmaxf(x0.z, x0.w)),
                    fmaxf(fmaxf(x1.x, x1.y), fmaxf(x1.z, x1.w)));
    #pragma unroll
    for (int o = 16; o > 0; o >>= 1) m = fmaxf(m, __shfl_xor_sync(0xFFFFFFFF, m, o));
    if (lane == 0) red[warp] = m;
    __syncthreads();
    m = red[lane & 7];
    #pragma unroll
    for (int o = 4; o > 0; o >>= 1) m = fmaxf(m, __shfl_xor_sync(0xFFFFFFFF, m, o));

    x0.x = __expf(x0.x - m); x0.y = __expf(x0.y - m);
    x0.z = __expf(x0.z - m); x0.w = __expf(x0.w - m);
    x1.x = __expf(x1.x - m); x1.y = __expf(x1.y - m);
    x1.z = __expf(x1.z - m); x1.w = __expf(x1.w - m);

    float sum = (x0.x + x0.y) + (x0.z + x0.w) + (x1.x + x1.y) + (x1.z + x1.w);
    #pragma unroll
    for (int o = 16; o > 0; o >>= 1) sum += __shfl_xor_sync(0xFFFFFFFF, sum, o);
    __syncthreads();
    if (lane == 0) red[warp] = sum;
    __syncthreads();
    sum = red[lane & 7];
    #pragma unroll
    for (int o = 4; o > 0; o >>= 1) sum += __shfl_xor_sync(0xFFFFFFFF, sum, o);
    const float inv = 1.f / sum;

    __half2 h[4];
    h[0].x = __float2half(x0.x * inv); h[0].y = __float2half(x0.y * inv);
    h[1].x = __float2half(x0.z * inv); h[1].y = __float2half(x0.w * inv);
    h[2].x = __float2half(x1.x * inv); h[2].y = __float2half(x1.y * inv);
    h[3].x = __float2half(x1.z * inv); h[3].y = __float2half(x1.w * inv);

    uint2* hp = (uint2*)(attn + rbase);
    uint2 hv0, hv1;
    hv0.x = *(uint32_t*)&h[0]; hv0.y = *(uint32_t*)&h[1];
    hv1.x = *(uint32_t*)&h[2]; hv1.y = *(uint32_t*)&h[3];
    hp[tid] = hv0; hp[tid + 256] = hv1;
}

// ---------------- launch ----------------
extern "C" void kernel_launch(void* const* d_in, const int* in_sizes, int n_in,
                              void* d_out, int out_size)
{
    (void)in_sizes; (void)n_in; (void)out_size;
    const float* query   = (const float*)d_in[0];
    const float* context = (const float*)d_in[1];
    const float* Wq      = (const float*)d_in[2];
    const float* bq      = (const float*)d_in[3];
    const float* Wv      = (const float*)d_in[4];
    const float* bv      = (const float*)d_in[5];
    const float* Wo      = (const float*)d_in[6];
    const float* bo      = (const float*)d_in[7];
    float* out = (float*)d_out;

    __half *qry,*ctx,*wq,*wv,*wo,*q,*vT,*attn,*h;
    float* s;
    cudaGetSymbolAddress((void**)&qry, g_qry);
    cudaGetSymbolAddress((void**)&ctx, g_ctx);
    cudaGetSymbolAddress((void**)&wq, g_wq);
    cudaGetSymbolAddress((void**)&wv, g_wv);
    cudaGetSymbolAddress((void**)&wo, g_wo);
    cudaGetSymbolAddress((void**)&q,  g_q);
    cudaGetSymbolAddress((void**)&vT, g_vT);
    cudaGetSymbolAddress((void**)&attn, g_attn);
    cudaGetSymbolAddress((void**)&h, g_h);
    cudaGetSymbolAddress((void**)&s, g_s);

    cudaFuncSetAttribute((const void*)mma_gemm<0>, cudaFuncAttributeMaxDynamicSharedMemorySize, SMEM_G);
    cudaFuncSetAttribute((const void*)mma_gemm<1>, cudaFuncAttributeMaxDynamicSharedMemorySize, SMEM_G);
    cudaFuncSetAttribute((const void*)qv_gemm,     cudaFuncAttributeMaxDynamicSharedMemorySize, SMEM_G);

    const float scale = 1.0f / sqrtf((float)DDIM);

    // 0) round all fp32 inputs -> fp16 (one launch)
    {
        int total = 2 * NQ4 + 3 * NW4;
        round_all_kernel<<<(total + 255) / 256, 256>>>(
            query, context, Wq, Wv, Wo,
            qry, ctx, wq, wv, wo);
    }

    // 1+2) q = round(qry@Wq^T + bq)  AND  v^T = round((ctx@Wv^T + bv)^T)
    qv_gemm<<<dim3(DDIM/128, MFLAT/128, 2), 256, SMEM_G>>>(
        qry, wq, bq, q, ctx, wv, bv, vT);

    // 3) scores = scale * q @ ctx^T  (batched) -> fp32 s
    mma_gemm<0><<<dim3(NSEQ/128, NSEQ/128, BB), 256, SMEM_G>>>(
        q, ctx, nullptr, s, nullptr,
        NSEQ, NSEQ, DDIM, scale,
        (long)NSEQ * DDIM, (long)NSEQ * DDIM, (long)NSEQ * NSEQ);

    // 4) softmax rows -> rounded attn
    softmax_round_kernel<<<BB * NSEQ, 256>>>(s, attn);

    // 5) h = attn @ (v^T)^T  (batched) -> rounded h
    mma_gemm<1><<<dim3(DDIM/128, NSEQ/128, BB), 256, SMEM_G>>>(
        attn, vT, nullptr, nullptr, h,
        NSEQ, DDIM, NSEQ, 1.0f,
        (long)NSEQ * NSEQ, (long)DDIM * NSEQ, (long)NSEQ * DDIM);

    // 6) out = h @ Wo^T + bo -> fp32
    mma_gemm<0><<<dim3(DDIM/128, MFLAT/128, 1), 256, SMEM_G>>>(
        h, wo, bo, out, nullptr,
        MFLAT, DDIM, DDIM, 1.0f, 0, 0, 0);
}

// round 13
// speedup vs baseline: 5.4234x; 1.0476x over previous
#include <cuda_runtime.h>
#include <cuda_fp16.h>
#include <cstdint>
#include <math.h>

#define BB 8
#define NSEQ 2048
#define DDIM 512
#define MFLAT (BB*NSEQ)

// ---------------- scratch (device globals: allocation-free) ----------------
__device__ __half g_qry[MFLAT*DDIM], g_ctx[MFLAT*DDIM];
__device__ __half g_wq[DDIM*DDIM], g_wo[DDIM*DDIM];
__device__ __half g_wvT[DDIM*DDIM];          // Wv transposed: wvT[d*512+f] = Wv[f*512+d]
__device__ __half g_wp[DDIM*DDIM];           // W' = Wo @ Wv, row-major [e,d]
__device__ float  g_b2[DDIM];                // b'' = Wo@bv + bo
__device__ __half g_q[MFLAT*DDIM];
__device__ __half g_uT[MFLAT*DDIM];          // u^T per batch [DDIM, NSEQ], u = ctx @ W'^T
__device__ float  g_s[(size_t)BB*NSEQ*NSEQ];
__device__ __half g_attn[(size_t)BB*NSEQ*NSEQ];

// ---------------- helpers ----------------
__device__ __forceinline__ uint32_t smem_u32(const void* p){
    uint32_t a;
    asm("{ .reg .u64 t; cvta.to.shared.u64 t, %1; cvt.u32.u64 %0, t; }" : "=r"(a) : "l"(p));
    return a;
}

#define CP_ASYNC16(sm, gm) \
    asm volatile("cp.async.cg.shared.global [%0], [%1], 16;" :: "r"(sm), "l"(gm))
#define CP_COMMIT() asm volatile("cp.async.commit_group;" ::: "memory")
#define CP_WAIT2()  asm volatile("cp.async.wait_group 2;" ::: "memory")
#define CP_WAIT1()  asm volatile("cp.async.wait_group 1;" ::: "memory")
#define CP_WAIT0()  asm volatile("cp.async.wait_group 0;" ::: "memory")

__device__ __forceinline__ void ldmatrix_x4(uint32_t& r0, uint32_t& r1, uint32_t& r2, uint32_t& r3, uint32_t addr){
    asm volatile("ldmatrix.sync.aligned.m8n8.x4.shared.b16 {%0,%1,%2,%3}, [%4];"
        : "=r"(r0), "=r"(r1), "=r"(r2), "=r"(r3) : "r"(addr));
}
__device__ __forceinline__ void mma_f16(float* c, const uint32_t* a, const uint32_t* b){
    asm volatile(
        "mma.sync.aligned.m16n8k16.row.col.f32.f16.f16.f32 "
        "{%0,%1,%2,%3}, {%4,%5,%6,%7}, {%8,%9}, {%0,%1,%2,%3};"
        : "+f"(c[0]), "+f"(c[1]), "+f"(c[2]), "+f"(c[3])
        : "r"(a[0]), "r"(a[1]), "r"(a[2]), "r"(a[3]), "r"(b[0]), "r"(b[1]));
}

// ---------------- GEMM config (CTA 128x128, warp 64x32, BK=32, 4 stages) ----------------
#define PITCH 80
#define TILEB (128*PITCH)
#define STAGEB (2*TILEB)
#define NSTAGE 4
#define SMEM_G (NSTAGE*STAGEB)     // 81920 B -> 2 CTAs/SM

// Mainloop: acc += A @ B^T (single product). One __syncthreads per iter.
#define GEMM_MAINLOOP(Aop, Bop, Kdim)                                                \
    const int T = (Kdim) >> 5;                                                       \
    const int ldRow = tid >> 1;                                                      \
    const int ldOff = (tid & 1) * 32;                                                \
    auto issue = [&](int t){                                                         \
        const int st = t & 3;                                                        \
        const int kk = t << 5;                                                       \
        const __half* Ap = (Aop) + (long)(rowBase + ldRow) * (Kdim) + kk + (ldOff >> 1); \
        const __half* Bp = (Bop) + (long)(colBase + ldRow) * (Kdim) + kk + (ldOff >> 1); \
        const uint32_t sa = smBase + st * STAGEB + ldRow * PITCH + ldOff;            \
        const uint32_t sb = sa + TILEB;                                              \
        CP_ASYNC16(sa,      Ap);                                                     \
        CP_ASYNC16(sa + 16, Ap + 8);                                                 \
        CP_ASYNC16(sb,      Bp);                                                     \
        CP_ASYNC16(sb + 16, Bp + 8);                                                 \
        CP_COMMIT();                                                                 \
    };                                                                               \
    issue(0); issue(1); issue(2);                                                    \
    const uint32_t aLaneOff = (uint32_t)(warpM*64 + (lane & 15)) * PITCH + ((lane >> 4) & 1) * 16; \
    const uint32_t bLaneOff = (uint32_t)(warpN*32 + (lane & 7) + ((lane >> 4) & 1) * 8) * PITCH    \
                            + ((lane >> 3) & 1) * 16;                                \
    for (int t = 0; t < T; t++) {                                                    \
        const int rem = T - 1 - t;                                                   \
        if (rem >= 2) { CP_WAIT2(); } else if (rem == 1) { CP_WAIT1(); } else { CP_WAIT0(); } \
        __syncthreads();                                                             \
        if (t + 3 < T) issue(t + 3);                                                 \
        const int st = t & 3;                                                        \
        const uint32_t aBase = smBase + st * STAGEB + aLaneOff;                      \
        const uint32_t bBase = smBase + st * STAGEB + TILEB + bLaneOff;              \
        _Pragma("unroll")                                                            \
        for (int ks = 0; ks < 2; ks++) {                                             \
            const uint32_t kByte = ks * 32;                                          \
            uint32_t afr[4][4];                                                      \
            _Pragma("unroll")                                                        \
            for (int mt = 0; mt < 4; mt++)                                           \
                ldmatrix_x4(afr[mt][0], afr[mt][1], afr[mt][2], afr[mt][3],          \
                            aBase + mt * 16 * PITCH + kByte);                        \
            uint32_t bfr[2][4];                                                      \
            _Pragma("unroll")                                                        \
            for (int p = 0; p < 2; p++)                                              \
                ldmatrix_x4(bfr[p][0], bfr[p][1], bfr[p][2], bfr[p][3],              \
                            bBase + p * 16 * PITCH + kByte);                         \
            _Pragma("unroll")                                                        \
            for (int mt = 0; mt < 4; mt++)                                           \
                _Pragma("unroll")                                                    \
                for (int nt = 0; nt < 4; nt++)                                       \
                    mma_f16(acc[mt][nt], afr[mt], &bfr[nt >> 1][(nt & 1) * 2]);      \
        }                                                                            \
    }

// ---------------- generic GEMM ----------------
// MODE 0: fp32 out (+bias, alpha). MODE 1: rounded fp16 out.
template<int MODE>
__global__ __launch_bounds__(256, 2)
void mma_gemm(const __half* __restrict__ A, const __half* __restrict__ B,
              const float* __restrict__ bias,
              float* __restrict__ outF, __half* __restrict__ outH,
              int M, int N, int K, float alpha,
              long sA, long sB, long sC)
{
    extern __shared__ __align__(128) char smem[];
    const int tid  = threadIdx.x;
    const int warp = tid >> 5;
    const int lane = tid & 31;
    const int warpM = warp >> 2;
    const int warpN = warp & 3;

    const int z = blockIdx.z;
    A += (long)z * sA;
    B += (long)z * sB;
    if (MODE == 0) { outF += (long)z * sC; } else { outH += (long)z * sC; }

    const int rowBase = blockIdx.y * 128;
    const int colBase = blockIdx.x * 128;
    const uint32_t smBase = smem_u32(smem);

    float acc[4][4][4];
    #pragma unroll
    for (int i = 0; i < 4; i++)
        #pragma unroll
        for (int j = 0; j < 4; j++)
            #pragma unroll
            for (int c = 0; c < 4; c++) acc[i][j][c] = 0.f;

    GEMM_MAINLOOP(A, B, K)

    #pragma unroll
    for (int mt = 0; mt < 4; mt++) {
        const int r0 = rowBase + warpM*64 + mt*16 + (lane >> 2);
        #pragma unroll
        for (int nt = 0; nt < 4; nt++) {
            const int gc = colBase + warpN*32 + nt*8 + (lane & 3)*2;
            float v00 = acc[mt][nt][0] * alpha;
            float v01 = acc[mt][nt][1] * alpha;
            float v10 = acc[mt][nt][2] * alpha;
            float v11 = acc[mt][nt][3] * alpha;
            if (bias) {
                const float b0 = bias[gc], b1 = bias[gc+1];
                v00 += b0; v01 += b1; v10 += b0; v11 += b1;
            }
            if (MODE == 0) {
                *(float2*)&outF[(long)r0 * N + gc]       = make_float2(v00, v01);
                *(float2*)&outF[(long)(r0+8) * N + gc]   = make_float2(v10, v11);
            } else {
                __half2 h;
                h.x = __float2half(v00); h.y = __float2half(v01);
                *(__half2*)&outH[(long)r0 * N + gc] = h;
                h.x = __float2half(v10); h.y = __float2half(v11);
                *(__half2*)&outH[(long)(r0+8) * N + gc] = h;
            }
        }
    }
}

// ---------------- combined Q/U projection (z=0: q rounded out, z=1: u^T rounded out) ----------
// z=0: q = round(qry @ Wq^T + bq)     [row-major]
// z=1: u = ctx @ W'^T  -> stored transposed per batch [DDIM, NSEQ] (no bias; b'' applied at end)
__global__ __launch_bounds__(256, 2)
void qu_gemm(const __half* __restrict__ qry, const __half* __restrict__ wq,
             const float* __restrict__ bq, __half* __restrict__ q,
             const __half* __restrict__ ctx, const __half* __restrict__ wp,
             __half* __restrict__ ut)
{
    extern __shared__ __align__(128) char smem[];
    const int tid  = threadIdx.x;
    const int warp = tid >> 5;
    const int lane = tid & 31;
    const int warpM = warp >> 2;
    const int warpN = warp & 3;
    const int isU = blockIdx.z;

    const int rowBase = blockIdx.y * 128;
    const int colBase = blockIdx.x * 128;
    const uint32_t smBase = smem_u32(smem);

    const __half* A = isU ? ctx : qry;
    const __half* B = isU ? wp  : wq;

    float acc[4][4][4];
    #pragma unroll
    for (int i = 0; i < 4; i++)
        #pragma unroll
        for (int j = 0; j < 4; j++)
            #pragma unroll
            for (int c = 0; c < 4; c++) acc[i][j][c] = 0.f;

    GEMM_MAINLOOP(A, B, DDIM)

    #pragma unroll
    for (int mt = 0; mt < 4; mt++) {
        const int r0 = rowBase + warpM*64 + mt*16 + (lane >> 2);
        #pragma unroll
        for (int nt = 0; nt < 4; nt++) {
            const int gc = colBase + warpN*32 + nt*8 + (lane & 3)*2;
            float v00 = acc[mt][nt][0];
            float v01 = acc[mt][nt][1];
            float v10 = acc[mt][nt][2];
            float v11 = acc[mt][nt][3];
            if (!isU) {        // q = round(... + bq), row-major
                const float b0 = bq[gc], b1 = bq[gc+1];
                v00 += b0; v01 += b1; v10 += b0; v11 += b1;
                __half2 h;
                h.x = __float2half(v00); h.y = __float2half(v01);
                *(__half2*)&q[(long)r0 * DDIM + gc] = h;
                h.x = __float2half(v10); h.y = __float2half(v11);
                *(__half2*)&q[(long)(r0+8) * DDIM + gc] = h;
            } else {           // u^T per batch [DDIM, NSEQ], rounded fp16
                const int rows[2] = {r0, r0 + 8};
                const float vals[2][2] = {{v00, v01}, {v10, v11}};
                #pragma unroll
                for (int rr = 0; rr < 2; rr++) {
                    const int bb = rows[rr] >> 11, tok = rows[rr] & 2047;
                    const long base = (long)bb * (DDIM * NSEQ) + tok;
                    #pragma unroll
                    for (int cc = 0; cc < 2; cc++)
                        ut[base + (long)(gc + cc) * NSEQ] = __float2half(vals[rr][cc]);
                }
            }
        }
    }
}

// ---------------- fused input round (fp32 -> fp16); Wv also written transposed ----------------
#define NQ4 ((MFLAT*DDIM)/4)
#define NW4 ((DDIM*DDIM)/4)
__global__ __launch_bounds__(256)
void round_all_kernel(const float* __restrict__ query, const float* __restrict__ context,
                      const float* __restrict__ Wq, const float* __restrict__ Wv, const float* __restrict__ Wo,
                      __half* __restrict__ qry, __half* __restrict__ ctx,
                      __half* __restrict__ wq, __half* __restrict__ wvT, __half* __restrict__ wo)
{
    int i = blockIdx.x * blockDim.x + threadIdx.x;
    const float* src; __half* dst; int mode = 0;
    if (i < NQ4)                  { src = query;   dst = qry; }
    else if ((i -= NQ4) < NQ4)    { src = context; dst = ctx; }
    else if ((i -= NQ4) < NW4)    { src = Wq;      dst = wq; }
    else if ((i -= NW4) < NW4)    { src = Wv;      dst = wvT; mode = 1; }
    else if ((i -= NW4) < NW4)    { src = Wo;      dst = wo; }
    else return;
    float4 v = ((const float4*)src)[i];
    if (mode == 0) {
        __half2 h0, h1;
        h0.x = __float2half(v.x); h0.y = __float2half(v.y);
        h1.x = __float2half(v.z); h1.y = __float2half(v.w);
        ((__half2*)dst)[2*i]   = h0;
        ((__half2*)dst)[2*i+1] = h1;
    } else {
        // Wv[f, d0..d0+3] -> wvT[d, f] (scattered transposed stores)
        const int f  = (4*i) >> 9;          // / 512
        const int d0 = (4*i) & 511;
        dst[(long)(d0+0) * DDIM + f] = __float2half(v.x);
        dst[(long)(d0+1) * DDIM + f] = __float2half(v.y);
        dst[(long)(d0+2) * DDIM + f] = __float2half(v.z);
        dst[(long)(d0+3) * DDIM + f] = __float2half(v.w);
    }
}

// ---------------- b'' = Wo @ bv + bo (512 blocks x 128 threads) ----------------
__global__ __launch_bounds__(128)
void bias_fold_kernel(const float* __restrict__ Wo, const float* __restrict__ bv,
                      const float* __restrict__ bo, float* __restrict__ b2)
{
    const int e = blockIdx.x;
    const int tid = threadIdx.x;
    __shared__ float red[128];
    float s = 0.f;
    for (int f = tid; f < DDIM; f += 128)
        s += Wo[(long)e * DDIM + f] * bv[f];
    red[tid] = s; __syncthreads();
    for (int o = 64; o > 0; o >>= 1) {
        if (tid < o) red[tid] += red[tid + o];
        __syncthreads();
    }
    if (tid == 0) b2[e] = red[0] + bo[e];
}

// ---------------- softmax + round to fp16 (register-resident row, n=2048) ----------------
__global__ __launch_bounds__(256)
void softmax_round_kernel(const float* __restrict__ s, __half* __restrict__ attn)
{
    const long rbase = (long)blockIdx.x * NSEQ;
    const float* row = s + rbase;
    const int tid = threadIdx.x;
    const int warp = tid >> 5, lane = tid & 31;
    __shared__ float red[8];

    float4 x0 = ((const float4*)row)[tid];
    float4 x1 = ((const float4*)row)[tid + 256];

    float m = fmaxf(fmaxf(fmaxf(x0.x, x0.y), fmaxf(x0.z, x0.w)),
                    fmaxf(fmaxf(x1.x, x1.y), fmaxf(x1.z, x1.w)));
    #pragma unroll
    for (int o = 16; o > 0; o >>= 1) m = fmaxf(m, __shfl_xor_sync(0xFFFFFFFF, m, o));
    if (lane == 0) red[warp] = m;
    __syncthreads();
    m = red[lane & 7];
    #pragma unroll
    for (int o = 4; o > 0; o >>= 1) m = fmaxf(m, __shfl_xor_sync(0xFFFFFFFF, m, o));

    x0.x = __expf(x0.x - m); x0.y = __expf(x0.y - m);
    x0.z = __expf(x0.z - m); x0.w = __expf(x0.w - m);
    x1.x = __expf(x1.x - m); x1.y = __expf(x1.y - m);
    x1.z = __expf(x1.z - m); x1.w = __expf(x1.w - m);

    float sum = (x0.x + x0.y) + (x0.z + x0.w) + (x1.x + x1.y) + (x1.z + x1.w);
    #pragma unroll
    for (int o = 16; o > 0; o >>= 1) sum += __shfl_xor_sync(0xFFFFFFFF, sum, o);
    __syncthreads();
    if (lane == 0) red[warp] = sum;
    __syncthreads();
    sum = red[lane & 7];
    #pragma unroll
    for (int o = 4; o > 0; o >>= 1) sum += __shfl_xor_sync(0xFFFFFFFF, sum, o);
    const float inv = 1.f / sum;

    __half2 h[4];
    h[0].x = __float2half(x0.x * inv); h[0].y = __float2half(x0.y * inv);
    h[1].x = __float2half(x0.z * inv); h[1].y = __float2half(x0.w * inv);
    h[2].x = __float2half(x1.x * inv); h[2].y = __float2half(x1.y * inv);
    h[3].x = __float2half(x1.z * inv); h[3].y = __float2half(x1.w * inv);

    uint2* hp = (uint2*)(attn + rbase);
    uint2 hv0, hv1;
    hv0.x = *(uint32_t*)&h[0]; hv0.y = *(uint32_t*)&h[1];
    hv1.x = *(uint32_t*)&h[2]; hv1.y = *(uint32_t*)&h[3];
    hp[tid] = hv0; hp[tid + 256] = hv1;
}

// ---------------- launch ----------------
extern "C" void kernel_launch(void* const* d_in, const int* in_sizes, int n_in,
                              void* d_out, int out_size)
{
    (void)in_sizes; (void)n_in; (void)out_size;
    const float* query   = (const float*)d_in[0];
    const float* context = (const float*)d_in[1];
    const float* Wq      = (const float*)d_in[2];
    const float* bq      = (const float*)d_in[3];
    const float* Wv      = (const float*)d_in[4];
    const float* bv      = (const float*)d_in[5];
    const float* Wo      = (const float*)d_in[6];
    const float* bo      = (const float*)d_in[7];
    float* out = (float*)d_out;

    __half *qry,*ctx,*wq,*wvT,*wo,*wp,*q,*uT,*attn;
    float *s,*b2;
    cudaGetSymbolAddress((void**)&qry, g_qry);
    cudaGetSymbolAddress((void**)&ctx, g_ctx);
    cudaGetSymbolAddress((void**)&wq,  g_wq);
    cudaGetSymbolAddress((void**)&wvT, g_wvT);
    cudaGetSymbolAddress((void**)&wo,  g_wo);
    cudaGetSymbolAddress((void**)&wp,  g_wp);
    cudaGetSymbolAddress((void**)&q,   g_q);
    cudaGetSymbolAddress((void**)&uT,  g_uT);
    cudaGetSymbolAddress((void**)&attn,g_attn);
    cudaGetSymbolAddress((void**)&s,   g_s);
    cudaGetSymbolAddress((void**)&b2,  g_b2);

    cudaFuncSetAttribute((const void*)mma_gemm<0>, cudaFuncAttributeMaxDynamicSharedMemorySize, SMEM_G);
    cudaFuncSetAttribute((const void*)mma_gemm<1>, cudaFuncAttributeMaxDynamicSharedMemorySize, SMEM_G);
    cudaFuncSetAttribute((const void*)qu_gemm,     cudaFuncAttributeMaxDynamicSharedMemorySize, SMEM_G);

    const float scale = 1.0f / sqrtf((float)DDIM);

    // 0) round all fp32 inputs -> fp16 (Wv written transposed)
    {
        int total = 2 * NQ4 + 3 * NW4;
        round_all_kernel<<<(total + 255) / 256, 256>>>(
            query, context, Wq, Wv, Wo,
            qry, ctx, wq, wvT, wo);
    }

    // 0b) W' = Wo @ Wv  (tiny GEMM: A=wo [e,f], B=wvT [d,f] -> W'[e,d])
    mma_gemm<1><<<dim3(DDIM/128, DDIM/128, 1), 256, SMEM_G>>>(
        wo, wvT, nullptr, nullptr, wp,
        DDIM, DDIM, DDIM, 1.0f, 0, 0, 0);

    // 0c) b'' = Wo @ bv + bo
    bias_fold_kernel<<<DDIM, 128>>>(Wo, bv, bo, b2);

    // 1+2) q = round(qry@Wq^T + bq)  AND  u^T = round((ctx@W'^T)^T)
    qu_gemm<<<dim3(DDIM/128, MFLAT/128, 2), 256, SMEM_G>>>(
        qry, wq, bq, q, ctx, wp, uT);

    // 3) scores = scale * q @ ctx^T  (batched) -> fp32 s
    mma_gemm<0><<<dim3(NSEQ/128, NSEQ/128, BB), 256, SMEM_G>>>(
        q, ctx, nullptr, s, nullptr,
        NSEQ, NSEQ, DDIM, scale,
        (long)NSEQ * DDIM, (long)NSEQ * DDIM, (long)NSEQ * NSEQ);

    // 4) softmax rows -> rounded attn
    softmax_round_kernel<<<BB * NSEQ, 256>>>(s, attn);

    // 5) out = attn @ (u^T)^T + b''  (batched) -> fp32 out directly
    mma_gemm<0><<<dim3(DDIM/128, NSEQ/128, BB), 256, SMEM_G>>>(
        attn, uT, b2, out, nullptr,
        NSEQ, DDIM, NSEQ, 1.0f,
        (long)NSEQ * NSEQ, (long)DDIM * NSEQ, (long)NSEQ * DDIM);
}